// round 10
// baseline (speedup 1.0000x reference)
#include <cuda_runtime.h>
#include <cuda_fp16.h>
#include <math.h>
#include <stdint.h>

#define SQ   2048
#define DIM  1024
#define NH   16
#define HDK  64
#define MLPD 4096
#define QKVN 3072

// ---------------- scratch (no allocations allowed) ----------------
__device__ unsigned short g_h   [SQ*DIM];
__device__ unsigned short g_qkv [SQ*QKVN];
__device__ unsigned short g_ao  [SQ*DIM];
__device__ float          g_x1  [SQ*DIM];
__device__ unsigned short g_f   [SQ*MLPD];
__device__ unsigned short g_wqkv[QKVN*DIM];
__device__ unsigned short g_wo  [DIM*DIM];
__device__ unsigned short g_w1  [MLPD*DIM];
__device__ unsigned short g_w2  [DIM*MLPD];
__device__ float          g_bqkv[QKVN];

// ---------------- helpers ----------------
__device__ __forceinline__ uint32_t smem_u32(const void* p) {
    uint32_t a;
    asm("{ .reg .u64 t; cvta.to.shared.u64 t, %1; cvt.u32.u64 %0, t; }" : "=r"(a) : "l"(p));
    return a;
}

__device__ __forceinline__ void cp_async16(uint32_t sdst, const void* gsrc) {
    asm volatile("cp.async.cg.shared.global [%0], [%1], 16;" :: "r"(sdst), "l"(gsrc) : "memory");
}
#define CP_COMMIT() asm volatile("cp.async.commit_group;" ::: "memory")
#define CP_WAIT(n)  asm volatile("cp.async.wait_group %0;" :: "n"(n) : "memory")

#define LDSM4(r, addr) \
    asm volatile("ldmatrix.sync.aligned.m8n8.x4.shared.b16 {%0,%1,%2,%3}, [%4];" \
        : "=r"((r)[0]), "=r"((r)[1]), "=r"((r)[2]), "=r"((r)[3]) : "r"(addr))

#define LDSM4T(r, addr) \
    asm volatile("ldmatrix.sync.aligned.m8n8.x4.trans.shared.b16 {%0,%1,%2,%3}, [%4];" \
        : "=r"((r)[0]), "=r"((r)[1]), "=r"((r)[2]), "=r"((r)[3]) : "r"(addr))

#define MMA_F16(c, a, b0, b1) \
    asm volatile("mma.sync.aligned.m16n8k16.row.col.f32.f16.f16.f32 " \
        "{%0,%1,%2,%3}, {%4,%5,%6,%7}, {%8,%9}, {%0,%1,%2,%3};" \
        : "+f"((c)[0]), "+f"((c)[1]), "+f"((c)[2]), "+f"((c)[3]) \
        : "r"((a)[0]), "r"((a)[1]), "r"((a)[2]), "r"((a)[3]), "r"(b0), "r"(b1))

#define MMA_F16R(c, a0, a1, a2, a3, b0, b1) \
    asm volatile("mma.sync.aligned.m16n8k16.row.col.f32.f16.f16.f32 " \
        "{%0,%1,%2,%3}, {%4,%5,%6,%7}, {%8,%9}, {%0,%1,%2,%3};" \
        : "+f"((c)[0]), "+f"((c)[1]), "+f"((c)[2]), "+f"((c)[3]) \
        : "r"(a0), "r"(a1), "r"(a2), "r"(a3), "r"(b0), "r"(b1))

__device__ __forceinline__ unsigned short f2h(float v) {
    return __half_as_ushort(__float2half_rn(v));
}
__device__ __forceinline__ uint32_t pack2_h(float a, float b) {
    __half2 h = __floats2half2_rn(a, b);
    return *(uint32_t*)&h;
}

// ---------------- layernorm -> fp16 ----------------
__device__ __forceinline__ float block_sum_256(float v, float* sh) {
    int lane = threadIdx.x & 31, w = threadIdx.x >> 5;
    #pragma unroll
    for (int o = 16; o; o >>= 1) v += __shfl_xor_sync(0xffffffffu, v, o);
    __syncthreads();
    if (lane == 0) sh[w] = v;
    __syncthreads();
    float r = 0.f;
    #pragma unroll
    for (int i = 0; i < 8; i++) r += sh[i];
    return r;
}

__global__ void ln_h_kernel(const float* __restrict__ x, const float* __restrict__ g,
                            const float* __restrict__ b, unsigned short* __restrict__ oh) {
    __shared__ float sh[8];
    int row = blockIdx.x;
    const float* xr = x + (size_t)row * DIM;
    int t = threadIdx.x;
    float v0[4];
    float s = 0.f;
    #pragma unroll
    for (int u = 0; u < 4; u++) { v0[u] = xr[t + u * 256]; s += v0[u]; }
    s = block_sum_256(s, sh);
    float mean = s * (1.0f / DIM);
    float vs = 0.f;
    #pragma unroll
    for (int u = 0; u < 4; u++) { float d = v0[u] - mean; vs += d * d; }
    vs = block_sum_256(vs, sh);
    float rstd = rsqrtf(vs * (1.0f / DIM) + 1e-5f);
    #pragma unroll
    for (int u = 0; u < 4; u++) {
        int c = t + u * 256;
        oh[(size_t)row * DIM + c] = f2h((v0[u] - mean) * rstd * g[c] + b[c]);
    }
}

// ---------------- merged weight prep ----------------
__global__ void prep_kernel(const float* __restrict__ wq, const float* __restrict__ wk,
                            const float* __restrict__ wv, const float* __restrict__ wo,
                            const float* __restrict__ w1, const float* __restrict__ w2,
                            const float* __restrict__ bq, const float* __restrict__ bk,
                            const float* __restrict__ bv,
                            unsigned short* __restrict__ owqkv, unsigned short* __restrict__ owo,
                            unsigned short* __restrict__ ow1, unsigned short* __restrict__ ow2,
                            float* __restrict__ obqkv) {
    int bid = blockIdx.x;
    if (bid >= 12288) {
        int i = (bid - 12288) * 256 + threadIdx.y * 32 + threadIdx.x;
        if (i < DIM) obqkv[i] = bq[i];
        else if (i < 2 * DIM) obqkv[i] = bk[i - DIM];
        else obqkv[i] = bv[i - 2 * DIM];
        return;
    }
    const float* in;
    unsigned short* out;
    int R, C, l;
    if (bid < 4096) {
        l = bid & 1023;
        R = DIM; C = DIM;
        int m = bid >> 10;
        in  = (m == 0) ? wq : (m == 1) ? wk : (m == 2) ? wv : wo;
        out = (m == 3) ? owo : owqkv + (size_t)m * DIM * DIM;
    } else if (bid < 8192) {
        l = bid - 4096; R = DIM; C = MLPD; in = w1; out = ow1;
    } else {
        l = bid - 8192; R = MLPD; C = DIM; in = w2; out = ow2;
    }
    int nbx = C >> 5;
    int bx = l % nbx, by = l / nbx;
    __shared__ float t[32][33];
    int c0 = bx * 32, r0 = by * 32;
    #pragma unroll
    for (int u = 0; u < 4; u++) {
        int r = r0 + threadIdx.y + u * 8;
        t[threadIdx.y + u * 8][threadIdx.x] = in[(size_t)r * C + c0 + threadIdx.x];
    }
    __syncthreads();
    #pragma unroll
    for (int u = 0; u < 4; u++) {
        int c = c0 + threadIdx.y + u * 8;
        out[(size_t)c * R + r0 + threadIdx.x] = f2h(t[threadIdx.x][threadIdx.y + u * 8]);
    }
}

// ---------------- fp16 GEMM 128x128 (R7 double-barrier) ----------------
#define TILEB 10240u
#define STAGES 4
#define GEMM_SMEM (STAGES * 2 * 10240)

__global__ __launch_bounds__(256, 2)
void gemm_mma_kernel(const unsigned short* __restrict__ A, const unsigned short* __restrict__ B,
                     const float* __restrict__ bias, const float* __restrict__ res,
                     float* __restrict__ outF, unsigned short* __restrict__ outH,
                     int N, int K, int gelu) {
    extern __shared__ char smem[];
    const uint32_t sb = smem_u32(smem);
    const int tid  = threadIdx.x;
    const int wid  = tid >> 5;
    const int lane = tid & 31;
    const int wm = wid >> 2;
    const int wn = wid & 3;
    const int bm = blockIdx.y * 128;
    const int bn = blockIdx.x * 128;
    const int g  = lane >> 2;
    const int t4 = lane & 3;

    const uint32_t aOff = (uint32_t)((((lane >> 3) & 1) * 8 + (lane & 7)) * 80 + (lane >> 4) * 16);
    const uint32_t bOff = (uint32_t)(((lane >> 4) * 8 + (lane & 7)) * 80 + ((lane >> 3) & 1) * 16);

    float acc[4][4][4];
    #pragma unroll
    for (int i = 0; i < 4; i++)
        #pragma unroll
        for (int j = 0; j < 4; j++)
            #pragma unroll
            for (int q = 0; q < 4; q++) acc[i][j][q] = 0.f;

    const int NCH = K >> 5;
    const unsigned short* gsrc[2] = {A, B};
    const int rbase[2] = {bm, bn};

    auto load_chunk = [&](int stage, int k0) {
        #pragma unroll
        for (int t = 0; t < 2; t++) {
            uint32_t dst = sb + (uint32_t)(stage * 2 + t) * TILEB;
            const unsigned short* gp = gsrc[t];
            #pragma unroll
            for (int u = 0; u < 2; u++) {
                int idx = tid + 256 * u;
                int r = idx >> 2;
                int cc = idx & 3;
                cp_async16(dst + (uint32_t)(r * 80 + cc * 16),
                           gp + (size_t)(rbase[t] + r) * K + k0 + cc * 8);
            }
        }
        CP_COMMIT();
    };

    #pragma unroll
    for (int s = 0; s < STAGES; s++) load_chunk(s, s * 32);

    int st = 0;
    for (int i = 0; i < NCH; i++) {
        CP_WAIT(STAGES - 1);
        __syncthreads();

        const uint32_t aB = sb + (uint32_t)(st * 2) * TILEB;
        const uint32_t bB = aB + TILEB;

        #pragma unroll
        for (int ks = 0; ks < 2; ks++) {
            uint32_t bf[2][4];
            #pragma unroll
            for (int np = 0; np < 2; np++) {
                uint32_t o = (uint32_t)((wn * 32 + np * 16) * 80 + ks * 32) + bOff;
                LDSM4(bf[np], bB + o);
            }
            #pragma unroll
            for (int mt = 0; mt < 4; mt++) {
                uint32_t af[4];
                uint32_t o = (uint32_t)((wm * 64 + mt * 16) * 80 + ks * 32) + aOff;
                LDSM4(af, aB + o);
                #pragma unroll
                for (int nt = 0; nt < 4; nt++) {
                    int np = nt >> 1, sub = (nt & 1) * 2;
                    MMA_F16(acc[mt][nt], af, bf[np][sub], bf[np][sub + 1]);
                }
            }
        }
        __syncthreads();

        if (i + STAGES < NCH) load_chunk(st, (i + STAGES) * 32);
        else                  CP_COMMIT();
        st = (st + 1) & (STAGES - 1);
    }

    #pragma unroll
    for (int mt = 0; mt < 4; mt++) {
        int r0 = bm + wm * 64 + mt * 16 + g;
        #pragma unroll
        for (int nt = 0; nt < 4; nt++) {
            int c = bn + wn * 32 + nt * 8 + t4 * 2;
            float v[4];
            v[0] = acc[mt][nt][0] + bias[c];
            v[1] = acc[mt][nt][1] + bias[c + 1];
            v[2] = acc[mt][nt][2] + bias[c];
            v[3] = acc[mt][nt][3] + bias[c + 1];
            if (gelu) {
                #pragma unroll
                for (int q = 0; q < 4; q++)
                    v[q] = 0.5f * v[q] * (1.0f + erff(v[q] * 0.70710678118654752f));
            }
            if (res) {
                v[0] += res[(size_t)r0 * N + c];
                v[1] += res[(size_t)r0 * N + c + 1];
                v[2] += res[(size_t)(r0 + 8) * N + c];
                v[3] += res[(size_t)(r0 + 8) * N + c + 1];
            }
            if (outF) {
                *(float2*)(outF + (size_t)r0 * N + c)       = make_float2(v[0], v[1]);
                *(float2*)(outF + (size_t)(r0 + 8) * N + c) = make_float2(v[2], v[3]);
            } else {
                *(uint32_t*)(outH + (size_t)r0 * N + c)       = pack2_h(v[0], v[1]);
                *(uint32_t*)(outH + (size_t)(r0 + 8) * N + c) = pack2_h(v[2], v[3]);
            }
        }
    }
}

// ---------------- fp16 GEMM 128x64 (for N=1024 GEMMs: 256 CTAs) ----------------
#define TILEB_A 10240u
#define TILEB_B 5120u
#define STAGE64 15360u
#define GEMM64_SMEM (STAGES * 15360)

__global__ __launch_bounds__(256, 2)
void gemm_n64_kernel(const unsigned short* __restrict__ A, const unsigned short* __restrict__ B,
                     const float* __restrict__ bias, const float* __restrict__ res,
                     float* __restrict__ outF, unsigned short* __restrict__ outH,
                     int N, int K, int gelu) {
    extern __shared__ char smem[];
    const uint32_t sb = smem_u32(smem);
    const int tid  = threadIdx.x;
    const int wid  = tid >> 5;
    const int lane = tid & 31;
    const int wm = wid >> 1;          // 0..3 (32 rows each)
    const int wn = wid & 1;           // 0..1 (32 cols each)
    const int bm = blockIdx.y * 128;
    const int bn = blockIdx.x * 64;
    const int g  = lane >> 2;
    const int t4 = lane & 3;

    const uint32_t aOff = (uint32_t)((((lane >> 3) & 1) * 8 + (lane & 7)) * 80 + (lane >> 4) * 16);
    const uint32_t bOff = (uint32_t)(((lane >> 4) * 8 + (lane & 7)) * 80 + ((lane >> 3) & 1) * 16);

    float acc[2][4][4];
    #pragma unroll
    for (int i = 0; i < 2; i++)
        #pragma unroll
        for (int j = 0; j < 4; j++)
            #pragma unroll
            for (int q = 0; q < 4; q++) acc[i][j][q] = 0.f;

    const int NCH = K >> 5;

    auto load_chunk = [&](int stage, int k0) {
        uint32_t aDst = sb + (uint32_t)stage * STAGE64;
        uint32_t bDst = aDst + TILEB_A;
        // A: 128 rows x 4 chunks = 512 cp
        #pragma unroll
        for (int u = 0; u < 2; u++) {
            int idx = tid + 256 * u;
            int r = idx >> 2;
            int cc = idx & 3;
            cp_async16(aDst + (uint32_t)(r * 80 + cc * 16),
                       A + (size_t)(bm + r) * K + k0 + cc * 8);
        }
        // B: 64 rows x 4 chunks = 256 cp
        {
            int r = tid >> 2;
            int cc = tid & 3;
            cp_async16(bDst + (uint32_t)(r * 80 + cc * 16),
                       B + (size_t)(bn + r) * K + k0 + cc * 8);
        }
        CP_COMMIT();
    };

    #pragma unroll
    for (int s = 0; s < STAGES; s++) load_chunk(s, s * 32);

    int st = 0;
    for (int i = 0; i < NCH; i++) {
        CP_WAIT(STAGES - 1);
        __syncthreads();

        const uint32_t aB = sb + (uint32_t)st * STAGE64;
        const uint32_t bB = aB + TILEB_A;

        #pragma unroll
        for (int ks = 0; ks < 2; ks++) {
            uint32_t bf[2][4];
            #pragma unroll
            for (int np = 0; np < 2; np++) {
                uint32_t o = (uint32_t)((wn * 32 + np * 16) * 80 + ks * 32) + bOff;
                LDSM4(bf[np], bB + o);
            }
            #pragma unroll
            for (int mt = 0; mt < 2; mt++) {
                uint32_t af[4];
                uint32_t o = (uint32_t)((wm * 32 + mt * 16) * 80 + ks * 32) + aOff;
                LDSM4(af, aB + o);
                #pragma unroll
                for (int nt = 0; nt < 4; nt++) {
                    int np = nt >> 1, sub = (nt & 1) * 2;
                    MMA_F16(acc[mt][nt], af, bf[np][sub], bf[np][sub + 1]);
                }
            }
        }
        __syncthreads();

        if (i + STAGES < NCH) load_chunk(st, (i + STAGES) * 32);
        else                  CP_COMMIT();
        st = (st + 1) & (STAGES - 1);
    }

    #pragma unroll
    for (int mt = 0; mt < 2; mt++) {
        int r0 = bm + wm * 32 + mt * 16 + g;
        #pragma unroll
        for (int nt = 0; nt < 4; nt++) {
            int c = bn + wn * 32 + nt * 8 + t4 * 2;
            float v[4];
            v[0] = acc[mt][nt][0] + bias[c];
            v[1] = acc[mt][nt][1] + bias[c + 1];
            v[2] = acc[mt][nt][2] + bias[c];
            v[3] = acc[mt][nt][3] + bias[c + 1];
            if (gelu) {
                #pragma unroll
                for (int q = 0; q < 4; q++)
                    v[q] = 0.5f * v[q] * (1.0f + erff(v[q] * 0.70710678118654752f));
            }
            if (res) {
                v[0] += res[(size_t)r0 * N + c];
                v[1] += res[(size_t)r0 * N + c + 1];
                v[2] += res[(size_t)(r0 + 8) * N + c];
                v[3] += res[(size_t)(r0 + 8) * N + c + 1];
            }
            if (outF) {
                *(float2*)(outF + (size_t)r0 * N + c)       = make_float2(v[0], v[1]);
                *(float2*)(outF + (size_t)(r0 + 8) * N + c) = make_float2(v[2], v[3]);
            } else {
                *(uint32_t*)(outH + (size_t)r0 * N + c)       = pack2_h(v[0], v[1]);
                *(uint32_t*)(outH + (size_t)(r0 + 8) * N + c) = pack2_h(v[2], v[3]);
            }
        }
    }
}

// ---------------- flash attention, fp16, 128 q-rows / 256 threads ----------------
#define ATILE 9216u
#define ATT_SMEM (2 * 2 * 9216)

__global__ __launch_bounds__(256)
void attn_mma_kernel(const unsigned short* __restrict__ qkv,
                     unsigned short* __restrict__ O) {
    extern __shared__ char smem[];
    const uint32_t sb = smem_u32(smem);
    const int h  = blockIdx.y;
    const int q0 = blockIdx.x * 128;
    const int tid = threadIdx.x;
    const int w = tid >> 5, lane = tid & 31;
    const int g = lane >> 2, t4 = lane & 3;
    const int qcol = h * HDK, kcol = DIM + h * HDK, vcol = 2 * DIM + h * HDK;

    const uint32_t aOff = (uint32_t)((((lane >> 3) & 1) * 8 + (lane & 7)) * 144 + (lane >> 4) * 16);
    const uint32_t bOff = (uint32_t)(((lane >> 4) * 8 + (lane & 7)) * 144 + ((lane >> 3) & 1) * 16);
    const uint32_t vOff = (uint32_t)((lane & 15) * 144 + (lane >> 4) * 16);

    #define AK(s) (sb + (uint32_t)(s) * 2u * ATILE)
    #define AV(s) (AK(s) + ATILE)

    // stage Q (128 rows x 64 cols) through smem stage-0 region (18432 B contiguous)
    #pragma unroll
    for (int u = 0; u < 4; u++) {
        int idx = tid + u * 256;
        int row = idx >> 3, c16 = idx & 7;
        cp_async16(AK(0) + (uint32_t)(row * 144 + c16 * 16),
                   qkv + (size_t)(q0 + row) * QKVN + qcol + c16 * 8);
    }
    CP_COMMIT(); CP_WAIT(0); __syncthreads();

    uint32_t qh[4][4];
    #pragma unroll
    for (int ks = 0; ks < 4; ks++) {
        uint32_t o = (uint32_t)(w * 16 * 144 + ks * 32);
        LDSM4(qh[ks], AK(0) + o + aOff);
    }
    __syncthreads();

    auto load_kv = [&](int st, int kt) {
        #pragma unroll
        for (int u = 0; u < 2; u++) {
            int idx = tid + u * 256;
            int row = idx >> 3, c16 = idx & 7;
            uint32_t off = (uint32_t)(row * 144 + c16 * 16);
            cp_async16(AK(st) + off, qkv + (size_t)(kt + row) * QKVN + kcol + c16 * 8);
            cp_async16(AV(st) + off, qkv + (size_t)(kt + row) * QKVN + vcol + c16 * 8);
        }
        CP_COMMIT();
    };
    load_kv(0, 0);
    load_kv(1, 64);

    float of[8][4];
    #pragma unroll
    for (int j = 0; j < 8; j++)
        #pragma unroll
        for (int q = 0; q < 4; q++) of[j][q] = 0.f;
    float m0 = -1e30f, m1 = -1e30f, l0 = 0.f, l1 = 0.f;

    for (int it = 0; it < SQ / 64; it++) {
        CP_WAIT(1);
        __syncthreads();
        const int st = it & 1;

        float sf[8][4];
        #pragma unroll
        for (int j = 0; j < 8; j++)
            #pragma unroll
            for (int q = 0; q < 4; q++) sf[j][q] = 0.f;

        #pragma unroll
        for (int ks = 0; ks < 4; ks++) {
            #pragma unroll
            for (int nb = 0; nb < 4; nb++) {
                uint32_t kf[4];
                LDSM4(kf, AK(st) + (uint32_t)(nb * 16 * 144 + ks * 32) + bOff);
                MMA_F16(sf[2*nb],   qh[ks], kf[0], kf[1]);
                MMA_F16(sf[2*nb+1], qh[ks], kf[2], kf[3]);
            }
        }

        float mx0 = -1e30f, mx1 = -1e30f;
        #pragma unroll
        for (int j = 0; j < 8; j++) {
            #pragma unroll
            for (int q = 0; q < 4; q++) sf[j][q] *= 0.125f;
            mx0 = fmaxf(mx0, fmaxf(sf[j][0], sf[j][1]));
            mx1 = fmaxf(mx1, fmaxf(sf[j][2], sf[j][3]));
        }
        mx0 = fmaxf(mx0, __shfl_xor_sync(0xffffffffu, mx0, 1));
        mx0 = fmaxf(mx0, __shfl_xor_sync(0xffffffffu, mx0, 2));
        mx1 = fmaxf(mx1, __shfl_xor_sync(0xffffffffu, mx1, 1));
        mx1 = fmaxf(mx1, __shfl_xor_sync(0xffffffffu, mx1, 2));
        float mn0 = fmaxf(m0, mx0), mn1 = fmaxf(m1, mx1);
        float sc0 = __expf(m0 - mn0), sc1 = __expf(m1 - mn1);
        m0 = mn0; m1 = mn1;
        float s0 = 0.f, s1 = 0.f;
        #pragma unroll
        for (int j = 0; j < 8; j++) {
            sf[j][0] = __expf(sf[j][0] - mn0); s0 += sf[j][0];
            sf[j][1] = __expf(sf[j][1] - mn0); s0 += sf[j][1];
            sf[j][2] = __expf(sf[j][2] - mn1); s1 += sf[j][2];
            sf[j][3] = __expf(sf[j][3] - mn1); s1 += sf[j][3];
        }
        s0 += __shfl_xor_sync(0xffffffffu, s0, 1);
        s0 += __shfl_xor_sync(0xffffffffu, s0, 2);
        s1 += __shfl_xor_sync(0xffffffffu, s1, 1);
        s1 += __shfl_xor_sync(0xffffffffu, s1, 2);
        l0 = l0 * sc0 + s0;
        l1 = l1 * sc1 + s1;
        #pragma unroll
        for (int j = 0; j < 8; j++) {
            of[j][0] *= sc0; of[j][1] *= sc0;
            of[j][2] *= sc1; of[j][3] *= sc1;
        }

        #pragma unroll
        for (int jp = 0; jp < 4; jp++) {
            uint32_t p0 = pack2_h(sf[2*jp][0],   sf[2*jp][1]);
            uint32_t p1 = pack2_h(sf[2*jp][2],   sf[2*jp][3]);
            uint32_t p2 = pack2_h(sf[2*jp+1][0], sf[2*jp+1][1]);
            uint32_t p3 = pack2_h(sf[2*jp+1][2], sf[2*jp+1][3]);
            #pragma unroll
            for (int nb = 0; nb < 4; nb++) {
                uint32_t vf[4];
                LDSM4T(vf, AV(st) + (uint32_t)(jp * 16 * 144 + nb * 16 * 2) + vOff);
                MMA_F16R(of[2*nb],   p0, p1, p2, p3, vf[0], vf[1]);
                MMA_F16R(of[2*nb+1], p0, p1, p2, p3, vf[2], vf[3]);
            }
        }

        __syncthreads();
        if (it + 2 < SQ / 64) load_kv(st, (it + 2) * 64);
        else                  CP_COMMIT();
    }

    float inv0 = 1.0f / l0, inv1 = 1.0f / l1;
    int r0 = q0 + w * 16 + g;
    #pragma unroll
    for (int j = 0; j < 8; j++) {
        int d = 8 * j + 2 * t4;
        *(uint32_t*)(O + (size_t)h * SQ * HDK + (size_t)r0 * HDK + d) =
            pack2_h(of[j][0] * inv0, of[j][1] * inv0);
        *(uint32_t*)(O + (size_t)h * SQ * HDK + (size_t)(r0 + 8) * HDK + d) =
            pack2_h(of[j][2] * inv1, of[j][3] * inv1);
    }
}

// ---------------- launch ----------------
extern "C" void kernel_launch(void* const* d_in, const int* in_sizes, int n_in,
                              void* d_out, int out_size) {
    const float* x     = (const float*)d_in[0];
    const float* wq    = (const float*)d_in[1];
    const float* bq    = (const float*)d_in[2];
    const float* wk    = (const float*)d_in[3];
    const float* bk    = (const float*)d_in[4];
    const float* wv    = (const float*)d_in[5];
    const float* bv    = (const float*)d_in[6];
    const float* wo    = (const float*)d_in[7];
    const float* bo    = (const float*)d_in[8];
    const float* w1    = (const float*)d_in[9];
    const float* b1    = (const float*)d_in[10];
    const float* w2    = (const float*)d_in[11];
    const float* b2    = (const float*)d_in[12];
    const float* ln1_g = (const float*)d_in[13];
    const float* ln1_b = (const float*)d_in[14];
    const float* ln2_g = (const float*)d_in[15];
    const float* ln2_b = (const float*)d_in[16];
    float* out = (float*)d_out;

    unsigned short *hh, *qkv, *ao, *f, *wqkvh, *woh, *w1h, *w2h;
    float *x1, *bqkv;
    cudaGetSymbolAddress((void**)&hh,   g_h);
    cudaGetSymbolAddress((void**)&qkv,  g_qkv);
    cudaGetSymbolAddress((void**)&ao,   g_ao);
    cudaGetSymbolAddress((void**)&x1,   g_x1);
    cudaGetSymbolAddress((void**)&f,    g_f);
    cudaGetSymbolAddress((void**)&wqkvh, g_wqkv);
    cudaGetSymbolAddress((void**)&woh,  g_wo);
    cudaGetSymbolAddress((void**)&w1h,  g_w1);
    cudaGetSymbolAddress((void**)&w2h,  g_w2);
    cudaGetSymbolAddress((void**)&bqkv, g_bqkv);

    cudaFuncSetAttribute(gemm_mma_kernel,
                         cudaFuncAttributeMaxDynamicSharedMemorySize, GEMM_SMEM);
    cudaFuncSetAttribute(gemm_n64_kernel,
                         cudaFuncAttributeMaxDynamicSharedMemorySize, GEMM64_SMEM);
    cudaFuncSetAttribute(attn_mma_kernel,
                         cudaFuncAttributeMaxDynamicSharedMemorySize, ATT_SMEM);

    // prep
    ln_h_kernel<<<SQ, 256>>>(x, ln1_g, ln1_b, hh);
    prep_kernel<<<12300, dim3(32, 8)>>>(wq, wk, wv, wo, w1, w2, bq, bk, bv,
                                        wqkvh, woh, w1h, w2h, bqkv);
    // QKV fused GEMM -> fp16 (128x128 tiles)
    gemm_mma_kernel<<<dim3(QKVN/128, SQ/128), 256, GEMM_SMEM>>>(
        hh, wqkvh, bqkv, nullptr, nullptr, qkv, QKVN, DIM, 0);
    // attention -> ao fp16 (128 q-rows per CTA)
    attn_mma_kernel<<<dim3(SQ/128, NH), 256, ATT_SMEM>>>(qkv, ao);
    // O-proj + residual(x) -> x1 fp32 (128x64 tiles: 256 CTAs)
    gemm_n64_kernel<<<dim3(DIM/64, SQ/128), 256, GEMM64_SMEM>>>(
        ao, woh, bo, x, x1, nullptr, DIM, DIM, 0);
    // LN2 -> fp16
    ln_h_kernel<<<SQ, 256>>>(x1, ln2_g, ln2_b, hh);
    // FFN1 + GELU -> f fp16 (128x128 tiles)
    gemm_mma_kernel<<<dim3(MLPD/128, SQ/128), 256, GEMM_SMEM>>>(
        hh, w1h, b1, nullptr, nullptr, f, MLPD, DIM, 1);
    // FFN2 + residual(x1) -> out fp32 (128x64 tiles: 256 CTAs)
    gemm_n64_kernel<<<dim3(DIM/64, SQ/128), 256, GEMM64_SMEM>>>(
        f, w2h, b2, x1, out, nullptr, DIM, MLPD, 0);
}

// round 11
// speedup vs baseline: 1.5699x; 1.5699x over previous
#include <cuda_runtime.h>
#include <cuda_fp16.h>
#include <math.h>
#include <stdint.h>

#define SQ   2048
#define DIM  1024
#define NH   16
#define HDK  64
#define MLPD 4096
#define QKVN 3072

// ---------------- scratch (no allocations allowed) ----------------
__device__ unsigned short g_h   [SQ*DIM];
__device__ unsigned short g_qkv [SQ*QKVN];
__device__ unsigned short g_ao  [SQ*DIM];
__device__ float          g_x1  [SQ*DIM];
__device__ unsigned short g_f   [SQ*MLPD];
__device__ unsigned short g_wqkv[QKVN*DIM];
__device__ unsigned short g_wo  [DIM*DIM];
__device__ unsigned short g_w1  [MLPD*DIM];
__device__ unsigned short g_w2  [DIM*MLPD];
__device__ float          g_bqkv[QKVN];
__device__ float          g_part[2][SQ*DIM];   // split-K partials

// ---------------- helpers ----------------
__device__ __forceinline__ uint32_t smem_u32(const void* p) {
    uint32_t a;
    asm("{ .reg .u64 t; cvta.to.shared.u64 t, %1; cvt.u32.u64 %0, t; }" : "=r"(a) : "l"(p));
    return a;
}

__device__ __forceinline__ void cp_async16(uint32_t sdst, const void* gsrc) {
    asm volatile("cp.async.cg.shared.global [%0], [%1], 16;" :: "r"(sdst), "l"(gsrc) : "memory");
}
#define CP_COMMIT() asm volatile("cp.async.commit_group;" ::: "memory")
#define CP_WAIT(n)  asm volatile("cp.async.wait_group %0;" :: "n"(n) : "memory")

#define LDSM4(r, addr) \
    asm volatile("ldmatrix.sync.aligned.m8n8.x4.shared.b16 {%0,%1,%2,%3}, [%4];" \
        : "=r"((r)[0]), "=r"((r)[1]), "=r"((r)[2]), "=r"((r)[3]) : "r"(addr))

#define LDSM4T(r, addr) \
    asm volatile("ldmatrix.sync.aligned.m8n8.x4.trans.shared.b16 {%0,%1,%2,%3}, [%4];" \
        : "=r"((r)[0]), "=r"((r)[1]), "=r"((r)[2]), "=r"((r)[3]) : "r"(addr))

#define MMA_F16(c, a, b0, b1) \
    asm volatile("mma.sync.aligned.m16n8k16.row.col.f32.f16.f16.f32 " \
        "{%0,%1,%2,%3}, {%4,%5,%6,%7}, {%8,%9}, {%0,%1,%2,%3};" \
        : "+f"((c)[0]), "+f"((c)[1]), "+f"((c)[2]), "+f"((c)[3]) \
        : "r"((a)[0]), "r"((a)[1]), "r"((a)[2]), "r"((a)[3]), "r"(b0), "r"(b1))

#define MMA_F16R(c, a0, a1, a2, a3, b0, b1) \
    asm volatile("mma.sync.aligned.m16n8k16.row.col.f32.f16.f16.f32 " \
        "{%0,%1,%2,%3}, {%4,%5,%6,%7}, {%8,%9}, {%0,%1,%2,%3};" \
        : "+f"((c)[0]), "+f"((c)[1]), "+f"((c)[2]), "+f"((c)[3]) \
        : "r"(a0), "r"(a1), "r"(a2), "r"(a3), "r"(b0), "r"(b1))

__device__ __forceinline__ unsigned short f2h(float v) {
    return __half_as_ushort(__float2half_rn(v));
}
__device__ __forceinline__ uint32_t pack2_h(float a, float b) {
    __half2 h = __floats2half2_rn(a, b);
    return *(uint32_t*)&h;
}

// ---------------- layernorm -> fp16 ----------------
__device__ __forceinline__ float block_sum_256(float v, float* sh) {
    int lane = threadIdx.x & 31, w = threadIdx.x >> 5;
    #pragma unroll
    for (int o = 16; o; o >>= 1) v += __shfl_xor_sync(0xffffffffu, v, o);
    __syncthreads();
    if (lane == 0) sh[w] = v;
    __syncthreads();
    float r = 0.f;
    #pragma unroll
    for (int i = 0; i < 8; i++) r += sh[i];
    return r;
}

__global__ void ln_h_kernel(const float* __restrict__ x, const float* __restrict__ g,
                            const float* __restrict__ b, unsigned short* __restrict__ oh) {
    __shared__ float sh[8];
    int row = blockIdx.x;
    const float* xr = x + (size_t)row * DIM;
    int t = threadIdx.x;
    float v0[4];
    float s = 0.f;
    #pragma unroll
    for (int u = 0; u < 4; u++) { v0[u] = xr[t + u * 256]; s += v0[u]; }
    s = block_sum_256(s, sh);
    float mean = s * (1.0f / DIM);
    float vs = 0.f;
    #pragma unroll
    for (int u = 0; u < 4; u++) { float d = v0[u] - mean; vs += d * d; }
    vs = block_sum_256(vs, sh);
    float rstd = rsqrtf(vs * (1.0f / DIM) + 1e-5f);
    #pragma unroll
    for (int u = 0; u < 4; u++) {
        int c = t + u * 256;
        oh[(size_t)row * DIM + c] = f2h((v0[u] - mean) * rstd * g[c] + b[c]);
    }
}

// ---------------- merged weight prep ----------------
__global__ void prep_kernel(const float* __restrict__ wq, const float* __restrict__ wk,
                            const float* __restrict__ wv, const float* __restrict__ wo,
                            const float* __restrict__ w1, const float* __restrict__ w2,
                            const float* __restrict__ bq, const float* __restrict__ bk,
                            const float* __restrict__ bv,
                            unsigned short* __restrict__ owqkv, unsigned short* __restrict__ owo,
                            unsigned short* __restrict__ ow1, unsigned short* __restrict__ ow2,
                            float* __restrict__ obqkv) {
    int bid = blockIdx.x;
    if (bid >= 12288) {
        int i = (bid - 12288) * 256 + threadIdx.y * 32 + threadIdx.x;
        if (i < DIM) obqkv[i] = bq[i];
        else if (i < 2 * DIM) obqkv[i] = bk[i - DIM];
        else obqkv[i] = bv[i - 2 * DIM];
        return;
    }
    const float* in;
    unsigned short* out;
    int R, C, l;
    if (bid < 4096) {
        l = bid & 1023;
        R = DIM; C = DIM;
        int m = bid >> 10;
        in  = (m == 0) ? wq : (m == 1) ? wk : (m == 2) ? wv : wo;
        out = (m == 3) ? owo : owqkv + (size_t)m * DIM * DIM;
    } else if (bid < 8192) {
        l = bid - 4096; R = DIM; C = MLPD; in = w1; out = ow1;
    } else {
        l = bid - 8192; R = MLPD; C = DIM; in = w2; out = ow2;
    }
    int nbx = C >> 5;
    int bx = l % nbx, by = l / nbx;
    __shared__ float t[32][33];
    int c0 = bx * 32, r0 = by * 32;
    #pragma unroll
    for (int u = 0; u < 4; u++) {
        int r = r0 + threadIdx.y + u * 8;
        t[threadIdx.y + u * 8][threadIdx.x] = in[(size_t)r * C + c0 + threadIdx.x];
    }
    __syncthreads();
    #pragma unroll
    for (int u = 0; u < 4; u++) {
        int c = c0 + threadIdx.y + u * 8;
        out[(size_t)c * R + r0 + threadIdx.x] = f2h(t[threadIdx.x][threadIdx.y + u * 8]);
    }
}

// ---------------- fp16 GEMM 128x128 (R7 double-barrier), optional split-K ----------------
// K = iteration extent per z-slice; ld = row stride of A/B in elements.
// If outP != null: write raw fp32 partials to outP + z*SQ*N (no bias/res/gelu).
#define TILEB 10240u
#define STAGES 4
#define GEMM_SMEM (STAGES * 2 * 10240)

__global__ __launch_bounds__(256, 2)
void gemm_mma_kernel(const unsigned short* __restrict__ A, const unsigned short* __restrict__ B,
                     const float* __restrict__ bias, const float* __restrict__ res,
                     float* __restrict__ outF, unsigned short* __restrict__ outH,
                     float* __restrict__ outP,
                     int N, int K, int ld, int gelu) {
    extern __shared__ char smem[];
    const uint32_t sb = smem_u32(smem);
    const int tid  = threadIdx.x;
    const int wid  = tid >> 5;
    const int lane = tid & 31;
    const int wm = wid >> 2;
    const int wn = wid & 3;
    const int bm = blockIdx.y * 128;
    const int bn = blockIdx.x * 128;
    const int g  = lane >> 2;
    const int t4 = lane & 3;

    // split-K offset along the row
    const unsigned short* Az = A + (size_t)blockIdx.z * K;
    const unsigned short* Bz = B + (size_t)blockIdx.z * K;

    const uint32_t aOff = (uint32_t)((((lane >> 3) & 1) * 8 + (lane & 7)) * 80 + (lane >> 4) * 16);
    const uint32_t bOff = (uint32_t)(((lane >> 4) * 8 + (lane & 7)) * 80 + ((lane >> 3) & 1) * 16);

    float acc[4][4][4];
    #pragma unroll
    for (int i = 0; i < 4; i++)
        #pragma unroll
        for (int j = 0; j < 4; j++)
            #pragma unroll
            for (int q = 0; q < 4; q++) acc[i][j][q] = 0.f;

    const int NCH = K >> 5;
    const unsigned short* gsrc[2] = {Az, Bz};
    const int rbase[2] = {bm, bn};

    auto load_chunk = [&](int stage, int k0) {
        #pragma unroll
        for (int t = 0; t < 2; t++) {
            uint32_t dst = sb + (uint32_t)(stage * 2 + t) * TILEB;
            const unsigned short* gp = gsrc[t];
            #pragma unroll
            for (int u = 0; u < 2; u++) {
                int idx = tid + 256 * u;
                int r = idx >> 2;
                int cc = idx & 3;
                cp_async16(dst + (uint32_t)(r * 80 + cc * 16),
                           gp + (size_t)(rbase[t] + r) * ld + k0 + cc * 8);
            }
        }
        CP_COMMIT();
    };

    #pragma unroll
    for (int s = 0; s < STAGES; s++) load_chunk(s, s * 32);

    int st = 0;
    for (int i = 0; i < NCH; i++) {
        CP_WAIT(STAGES - 1);
        __syncthreads();

        const uint32_t aB = sb + (uint32_t)(st * 2) * TILEB;
        const uint32_t bB = aB + TILEB;

        #pragma unroll
        for (int ks = 0; ks < 2; ks++) {
            uint32_t bf[2][4];
            #pragma unroll
            for (int np = 0; np < 2; np++) {
                uint32_t o = (uint32_t)((wn * 32 + np * 16) * 80 + ks * 32) + bOff;
                LDSM4(bf[np], bB + o);
            }
            #pragma unroll
            for (int mt = 0; mt < 4; mt++) {
                uint32_t af[4];
                uint32_t o = (uint32_t)((wm * 64 + mt * 16) * 80 + ks * 32) + aOff;
                LDSM4(af, aB + o);
                #pragma unroll
                for (int nt = 0; nt < 4; nt++) {
                    int np = nt >> 1, sub = (nt & 1) * 2;
                    MMA_F16(acc[mt][nt], af, bf[np][sub], bf[np][sub + 1]);
                }
            }
        }
        __syncthreads();

        if (i + STAGES < NCH) load_chunk(st, (i + STAGES) * 32);
        else                  CP_COMMIT();
        st = (st + 1) & (STAGES - 1);
    }

    if (outP) {
        // raw fp32 partial, no epilogue
        float* po = outP + (size_t)blockIdx.z * SQ * N;
        #pragma unroll
        for (int mt = 0; mt < 4; mt++) {
            int r0 = bm + wm * 64 + mt * 16 + g;
            #pragma unroll
            for (int nt = 0; nt < 4; nt++) {
                int c = bn + wn * 32 + nt * 8 + t4 * 2;
                *(float2*)(po + (size_t)r0 * N + c)       = make_float2(acc[mt][nt][0], acc[mt][nt][1]);
                *(float2*)(po + (size_t)(r0 + 8) * N + c) = make_float2(acc[mt][nt][2], acc[mt][nt][3]);
            }
        }
        return;
    }

    #pragma unroll
    for (int mt = 0; mt < 4; mt++) {
        int r0 = bm + wm * 64 + mt * 16 + g;
        #pragma unroll
        for (int nt = 0; nt < 4; nt++) {
            int c = bn + wn * 32 + nt * 8 + t4 * 2;
            float v[4];
            v[0] = acc[mt][nt][0] + bias[c];
            v[1] = acc[mt][nt][1] + bias[c + 1];
            v[2] = acc[mt][nt][2] + bias[c];
            v[3] = acc[mt][nt][3] + bias[c + 1];
            if (gelu) {
                #pragma unroll
                for (int q = 0; q < 4; q++)
                    v[q] = 0.5f * v[q] * (1.0f + erff(v[q] * 0.70710678118654752f));
            }
            if (res) {
                v[0] += res[(size_t)r0 * N + c];
                v[1] += res[(size_t)r0 * N + c + 1];
                v[2] += res[(size_t)(r0 + 8) * N + c];
                v[3] += res[(size_t)(r0 + 8) * N + c + 1];
            }
            if (outF) {
                *(float2*)(outF + (size_t)r0 * N + c)       = make_float2(v[0], v[1]);
                *(float2*)(outF + (size_t)(r0 + 8) * N + c) = make_float2(v[2], v[3]);
            } else {
                *(uint32_t*)(outH + (size_t)r0 * N + c)       = pack2_h(v[0], v[1]);
                *(uint32_t*)(outH + (size_t)(r0 + 8) * N + c) = pack2_h(v[2], v[3]);
            }
        }
    }
}

// ---------------- split-K reduce: out = p0 + p1 + bias + res ----------------
__global__ void reduce2_kernel(const float* __restrict__ p0, const float* __restrict__ p1,
                               const float* __restrict__ bias, const float* __restrict__ res,
                               float* __restrict__ out) {
    size_t i = ((size_t)blockIdx.x * 256 + threadIdx.x) * 4;
    int c = (int)(i & (DIM - 1));
    float4 a = *(const float4*)(p0 + i);
    float4 b = *(const float4*)(p1 + i);
    float4 r = *(const float4*)(res + i);
    float4 o;
    o.x = a.x + b.x + bias[c]     + r.x;
    o.y = a.y + b.y + bias[c + 1] + r.y;
    o.z = a.z + b.z + bias[c + 2] + r.z;
    o.w = a.w + b.w + bias[c + 3] + r.w;
    *(float4*)(out + i) = o;
}

// ---------------- flash attention (R9: 64 q-rows, 128 threads, 2-stage) ----------------
#define ATILE 9216u
#define ATT_SMEM (2 * 2 * 9216)

__global__ __launch_bounds__(128)
void attn_mma_kernel(const unsigned short* __restrict__ qkv,
                     unsigned short* __restrict__ O) {
    extern __shared__ char smem[];
    const uint32_t sb = smem_u32(smem);
    const int h  = blockIdx.y;
    const int q0 = blockIdx.x * 64;
    const int tid = threadIdx.x;
    const int w = tid >> 5, lane = tid & 31;
    const int g = lane >> 2, t4 = lane & 3;
    const int qcol = h * HDK, kcol = DIM + h * HDK, vcol = 2 * DIM + h * HDK;

    const uint32_t aOff = (uint32_t)((((lane >> 3) & 1) * 8 + (lane & 7)) * 144 + (lane >> 4) * 16);
    const uint32_t bOff = (uint32_t)(((lane >> 4) * 8 + (lane & 7)) * 144 + ((lane >> 3) & 1) * 16);
    const uint32_t vOff = (uint32_t)((lane & 15) * 144 + (lane >> 4) * 16);

    #define AK(s) (sb + (uint32_t)(s) * 2u * ATILE)
    #define AV(s) (AK(s) + ATILE)

    #pragma unroll
    for (int u = 0; u < 4; u++) {
        int idx = tid + u * 128;
        int row = idx >> 3, c16 = idx & 7;
        cp_async16(AK(0) + (uint32_t)(row * 144 + c16 * 16),
                   qkv + (size_t)(q0 + row) * QKVN + qcol + c16 * 8);
    }
    CP_COMMIT(); CP_WAIT(0); __syncthreads();

    uint32_t qh[4][4];
    #pragma unroll
    for (int ks = 0; ks < 4; ks++) {
        uint32_t o = (uint32_t)(w * 16 * 144 + ks * 32);
        LDSM4(qh[ks], AK(0) + o + aOff);
    }
    __syncthreads();

    auto load_kv = [&](int st, int kt) {
        #pragma unroll
        for (int u = 0; u < 4; u++) {
            int idx = tid + u * 128;
            int row = idx >> 3, c16 = idx & 7;
            uint32_t off = (uint32_t)(row * 144 + c16 * 16);
            cp_async16(AK(st) + off, qkv + (size_t)(kt + row) * QKVN + kcol + c16 * 8);
            cp_async16(AV(st) + off, qkv + (size_t)(kt + row) * QKVN + vcol + c16 * 8);
        }
        CP_COMMIT();
    };
    load_kv(0, 0);
    load_kv(1, 64);

    float of[8][4];
    #pragma unroll
    for (int j = 0; j < 8; j++)
        #pragma unroll
        for (int q = 0; q < 4; q++) of[j][q] = 0.f;
    float m0 = -1e30f, m1 = -1e30f, l0 = 0.f, l1 = 0.f;

    for (int it = 0; it < SQ / 64; it++) {
        CP_WAIT(1);
        __syncthreads();
        const int st = it & 1;

        float sf[8][4];
        #pragma unroll
        for (int j = 0; j < 8; j++)
            #pragma unroll
            for (int q = 0; q < 4; q++) sf[j][q] = 0.f;

        #pragma unroll
        for (int ks = 0; ks < 4; ks++) {
            #pragma unroll
            for (int nb = 0; nb < 4; nb++) {
                uint32_t kf[4];
                LDSM4(kf, AK(st) + (uint32_t)(nb * 16 * 144 + ks * 32) + bOff);
                MMA_F16(sf[2*nb],   qh[ks], kf[0], kf[1]);
                MMA_F16(sf[2*nb+1], qh[ks], kf[2], kf[3]);
            }
        }

        float mx0 = -1e30f, mx1 = -1e30f;
        #pragma unroll
        for (int j = 0; j < 8; j++) {
            #pragma unroll
            for (int q = 0; q < 4; q++) sf[j][q] *= 0.125f;
            mx0 = fmaxf(mx0, fmaxf(sf[j][0], sf[j][1]));
            mx1 = fmaxf(mx1, fmaxf(sf[j][2], sf[j][3]));
        }
        mx0 = fmaxf(mx0, __shfl_xor_sync(0xffffffffu, mx0, 1));
        mx0 = fmaxf(mx0, __shfl_xor_sync(0xffffffffu, mx0, 2));
        mx1 = fmaxf(mx1, __shfl_xor_sync(0xffffffffu, mx1, 1));
        mx1 = fmaxf(mx1, __shfl_xor_sync(0xffffffffu, mx1, 2));
        float mn0 = fmaxf(m0, mx0), mn1 = fmaxf(m1, mx1);
        float sc0 = __expf(m0 - mn0), sc1 = __expf(m1 - mn1);
        m0 = mn0; m1 = mn1;
        float s0 = 0.f, s1 = 0.f;
        #pragma unroll
        for (int j = 0; j < 8; j++) {
            sf[j][0] = __expf(sf[j][0] - mn0); s0 += sf[j][0];
            sf[j][1] = __expf(sf[j][1] - mn0); s0 += sf[j][1];
            sf[j][2] = __expf(sf[j][2] - mn1); s1 += sf[j][2];
            sf[j][3] = __expf(sf[j][3] - mn1); s1 += sf[j][3];
        }
        s0 += __shfl_xor_sync(0xffffffffu, s0, 1);
        s0 += __shfl_xor_sync(0xffffffffu, s0, 2);
        s1 += __shfl_xor_sync(0xffffffffu, s1, 1);
        s1 += __shfl_xor_sync(0xffffffffu, s1, 2);
        l0 = l0 * sc0 + s0;
        l1 = l1 * sc1 + s1;
        #pragma unroll
        for (int j = 0; j < 8; j++) {
            of[j][0] *= sc0; of[j][1] *= sc0;
            of[j][2] *= sc1; of[j][3] *= sc1;
        }

        #pragma unroll
        for (int jp = 0; jp < 4; jp++) {
            uint32_t p0 = pack2_h(sf[2*jp][0],   sf[2*jp][1]);
            uint32_t p1 = pack2_h(sf[2*jp][2],   sf[2*jp][3]);
            uint32_t p2 = pack2_h(sf[2*jp+1][0], sf[2*jp+1][1]);
            uint32_t p3 = pack2_h(sf[2*jp+1][2], sf[2*jp+1][3]);
            #pragma unroll
            for (int nb = 0; nb < 4; nb++) {
                uint32_t vf[4];
                LDSM4T(vf, AV(st) + (uint32_t)(jp * 16 * 144 + nb * 16 * 2) + vOff);
                MMA_F16R(of[2*nb],   p0, p1, p2, p3, vf[0], vf[1]);
                MMA_F16R(of[2*nb+1], p0, p1, p2, p3, vf[2], vf[3]);
            }
        }

        __syncthreads();
        if (it + 2 < SQ / 64) load_kv(st, (it + 2) * 64);
        else                  CP_COMMIT();
    }

    float inv0 = 1.0f / l0, inv1 = 1.0f / l1;
    int r0 = q0 + w * 16 + g;
    #pragma unroll
    for (int j = 0; j < 8; j++) {
        int d = 8 * j + 2 * t4;
        *(uint32_t*)(O + (size_t)h * SQ * HDK + (size_t)r0 * HDK + d) =
            pack2_h(of[j][0] * inv0, of[j][1] * inv0);
        *(uint32_t*)(O + (size_t)h * SQ * HDK + (size_t)(r0 + 8) * HDK + d) =
            pack2_h(of[j][2] * inv1, of[j][3] * inv1);
    }
}

// ---------------- launch ----------------
extern "C" void kernel_launch(void* const* d_in, const int* in_sizes, int n_in,
                              void* d_out, int out_size) {
    const float* x     = (const float*)d_in[0];
    const float* wq    = (const float*)d_in[1];
    const float* bq    = (const float*)d_in[2];
    const float* wk    = (const float*)d_in[3];
    const float* bk    = (const float*)d_in[4];
    const float* wv    = (const float*)d_in[5];
    const float* bv    = (const float*)d_in[6];
    const float* wo    = (const float*)d_in[7];
    const float* bo    = (const float*)d_in[8];
    const float* w1    = (const float*)d_in[9];
    const float* b1    = (const float*)d_in[10];
    const float* w2    = (const float*)d_in[11];
    const float* b2    = (const float*)d_in[12];
    const float* ln1_g = (const float*)d_in[13];
    const float* ln1_b = (const float*)d_in[14];
    const float* ln2_g = (const float*)d_in[15];
    const float* ln2_b = (const float*)d_in[16];
    float* out = (float*)d_out;

    unsigned short *hh, *qkv, *ao, *f, *wqkvh, *woh, *w1h, *w2h;
    float *x1, *bqkv, *part;
    cudaGetSymbolAddress((void**)&hh,   g_h);
    cudaGetSymbolAddress((void**)&qkv,  g_qkv);
    cudaGetSymbolAddress((void**)&ao,   g_ao);
    cudaGetSymbolAddress((void**)&x1,   g_x1);
    cudaGetSymbolAddress((void**)&f,    g_f);
    cudaGetSymbolAddress((void**)&wqkvh, g_wqkv);
    cudaGetSymbolAddress((void**)&woh,  g_wo);
    cudaGetSymbolAddress((void**)&w1h,  g_w1);
    cudaGetSymbolAddress((void**)&w2h,  g_w2);
    cudaGetSymbolAddress((void**)&bqkv, g_bqkv);
    cudaGetSymbolAddress((void**)&part, g_part);

    cudaFuncSetAttribute(gemm_mma_kernel,
                         cudaFuncAttributeMaxDynamicSharedMemorySize, GEMM_SMEM);
    cudaFuncSetAttribute(attn_mma_kernel,
                         cudaFuncAttributeMaxDynamicSharedMemorySize, ATT_SMEM);

    // prep
    ln_h_kernel<<<SQ, 256>>>(x, ln1_g, ln1_b, hh);
    prep_kernel<<<12300, dim3(32, 8)>>>(wq, wk, wv, wo, w1, w2, bq, bk, bv,
                                        wqkvh, woh, w1h, w2h, bqkv);
    // QKV fused GEMM -> fp16
    gemm_mma_kernel<<<dim3(QKVN/128, SQ/128), 256, GEMM_SMEM>>>(
        hh, wqkvh, bqkv, nullptr, nullptr, qkv, nullptr, QKVN, DIM, DIM, 0);
    // attention -> ao fp16 (R9 geometry)
    attn_mma_kernel<<<dim3(SQ/64, NH), 128, ATT_SMEM>>>(qkv, ao);
    // O-proj + residual(x) -> x1 fp32
    gemm_mma_kernel<<<dim3(DIM/128, SQ/128), 256, GEMM_SMEM>>>(
        ao, woh, bo, x, x1, nullptr, nullptr, DIM, DIM, DIM, 0);
    // LN2 -> fp16
    ln_h_kernel<<<SQ, 256>>>(x1, ln2_g, ln2_b, hh);
    // FFN1 + GELU -> f fp16
    gemm_mma_kernel<<<dim3(MLPD/128, SQ/128), 256, GEMM_SMEM>>>(
        hh, w1h, b1, nullptr, nullptr, f, nullptr, MLPD, DIM, DIM, 1);
    // FFN2 split-K=2 -> partials, then reduce(+bias+residual) -> out
    gemm_mma_kernel<<<dim3(DIM/128, SQ/128, 2), 256, GEMM_SMEM>>>(
        f, w2h, nullptr, nullptr, nullptr, nullptr, part, DIM, MLPD/2, MLPD, 0);
    reduce2_kernel<<<SQ * DIM / 1024, 256>>>(part, part + (size_t)SQ * DIM, b2, x1, out);
}

// round 12
// speedup vs baseline: 1.5965x; 1.0170x over previous
#include <cuda_runtime.h>
#include <cuda_fp16.h>
#include <math.h>
#include <stdint.h>

#define SQ   2048
#define DIM  1024
#define NH   16
#define HDK  64
#define MLPD 4096
#define QKVN 3072

// ---------------- scratch (no allocations allowed) ----------------
__device__ unsigned short g_h   [SQ*DIM];
__device__ unsigned short g_qkv [SQ*QKVN];
__device__ unsigned short g_ao  [SQ*DIM];
__device__ float          g_x1  [SQ*DIM];
__device__ unsigned short g_f   [SQ*MLPD];
__device__ unsigned short g_wqkv[QKVN*DIM];
__device__ unsigned short g_wo  [DIM*DIM];
__device__ unsigned short g_w1  [MLPD*DIM];
__device__ unsigned short g_w2  [DIM*MLPD];
__device__ float          g_bqkv[QKVN];
__device__ float          g_part[2][SQ*DIM];   // split-K partials

// ---------------- helpers ----------------
__device__ __forceinline__ uint32_t smem_u32(const void* p) {
    uint32_t a;
    asm("{ .reg .u64 t; cvta.to.shared.u64 t, %1; cvt.u32.u64 %0, t; }" : "=r"(a) : "l"(p));
    return a;
}

__device__ __forceinline__ void cp_async16(uint32_t sdst, const void* gsrc) {
    asm volatile("cp.async.cg.shared.global [%0], [%1], 16;" :: "r"(sdst), "l"(gsrc) : "memory");
}
#define CP_COMMIT() asm volatile("cp.async.commit_group;" ::: "memory")
#define CP_WAIT(n)  asm volatile("cp.async.wait_group %0;" :: "n"(n) : "memory")

#define LDSM4(r, addr) \
    asm volatile("ldmatrix.sync.aligned.m8n8.x4.shared.b16 {%0,%1,%2,%3}, [%4];" \
        : "=r"((r)[0]), "=r"((r)[1]), "=r"((r)[2]), "=r"((r)[3]) : "r"(addr))

#define LDSM4T(r, addr) \
    asm volatile("ldmatrix.sync.aligned.m8n8.x4.trans.shared.b16 {%0,%1,%2,%3}, [%4];" \
        : "=r"((r)[0]), "=r"((r)[1]), "=r"((r)[2]), "=r"((r)[3]) : "r"(addr))

#define MMA_F16(c, a, b0, b1) \
    asm volatile("mma.sync.aligned.m16n8k16.row.col.f32.f16.f16.f32 " \
        "{%0,%1,%2,%3}, {%4,%5,%6,%7}, {%8,%9}, {%0,%1,%2,%3};" \
        : "+f"((c)[0]), "+f"((c)[1]), "+f"((c)[2]), "+f"((c)[3]) \
        : "r"((a)[0]), "r"((a)[1]), "r"((a)[2]), "r"((a)[3]), "r"(b0), "r"(b1))

#define MMA_F16R(c, a0, a1, a2, a3, b0, b1) \
    asm volatile("mma.sync.aligned.m16n8k16.row.col.f32.f16.f16.f32 " \
        "{%0,%1,%2,%3}, {%4,%5,%6,%7}, {%8,%9}, {%0,%1,%2,%3};" \
        : "+f"((c)[0]), "+f"((c)[1]), "+f"((c)[2]), "+f"((c)[3]) \
        : "r"(a0), "r"(a1), "r"(a2), "r"(a3), "r"(b0), "r"(b1))

__device__ __forceinline__ unsigned short f2h(float v) {
    return __half_as_ushort(__float2half_rn(v));
}
__device__ __forceinline__ uint32_t pack2_h(float a, float b) {
    __half2 h = __floats2half2_rn(a, b);
    return *(uint32_t*)&h;
}

// ---------------- shared reduction ----------------
__device__ __forceinline__ float block_sum_256(float v, float* sh) {
    int lane = threadIdx.x & 31, w = threadIdx.x >> 5;
    #pragma unroll
    for (int o = 16; o; o >>= 1) v += __shfl_xor_sync(0xffffffffu, v, o);
    __syncthreads();
    if (lane == 0) sh[w] = v;
    __syncthreads();
    float r = 0.f;
    #pragma unroll
    for (int i = 0; i < 8; i++) r += sh[i];
    return r;
}

// ---------------- layernorm -> fp16 ----------------
__global__ void ln_h_kernel(const float* __restrict__ x, const float* __restrict__ g,
                            const float* __restrict__ b, unsigned short* __restrict__ oh) {
    __shared__ float sh[8];
    int row = blockIdx.x;
    const float* xr = x + (size_t)row * DIM;
    int t = threadIdx.x;
    float v0[4];
    float s = 0.f;
    #pragma unroll
    for (int u = 0; u < 4; u++) { v0[u] = xr[t + u * 256]; s += v0[u]; }
    s = block_sum_256(s, sh);
    float mean = s * (1.0f / DIM);
    float vs = 0.f;
    #pragma unroll
    for (int u = 0; u < 4; u++) { float d = v0[u] - mean; vs += d * d; }
    vs = block_sum_256(vs, sh);
    float rstd = rsqrtf(vs * (1.0f / DIM) + 1e-5f);
    #pragma unroll
    for (int u = 0; u < 4; u++) {
        int c = t + u * 256;
        oh[(size_t)row * DIM + c] = f2h((v0[u] - mean) * rstd * g[c] + b[c]);
    }
}

// ---------------- fused split-K reduce + residual + LN2 ----------------
// x1 = p0 + p1 + bias + res ; oh = f16(LN(x1; g, b2ln))
__global__ void reduce_ln_kernel(const float* __restrict__ p0, const float* __restrict__ p1,
                                 const float* __restrict__ bias, const float* __restrict__ res,
                                 const float* __restrict__ lng, const float* __restrict__ lnb,
                                 float* __restrict__ x1, unsigned short* __restrict__ oh) {
    __shared__ float sh[8];
    int row = blockIdx.x;
    int t = threadIdx.x;
    size_t base = (size_t)row * DIM;
    float v0[4];
    float s = 0.f;
    #pragma unroll
    for (int u = 0; u < 4; u++) {
        int c = t + u * 256;
        float v = p0[base + c] + p1[base + c] + bias[c] + res[base + c];
        v0[u] = v; s += v;
        x1[base + c] = v;
    }
    s = block_sum_256(s, sh);
    float mean = s * (1.0f / DIM);
    float vs = 0.f;
    #pragma unroll
    for (int u = 0; u < 4; u++) { float d = v0[u] - mean; vs += d * d; }
    vs = block_sum_256(vs, sh);
    float rstd = rsqrtf(vs * (1.0f / DIM) + 1e-5f);
    #pragma unroll
    for (int u = 0; u < 4; u++) {
        int c = t + u * 256;
        oh[base + c] = f2h((v0[u] - mean) * rstd * lng[c] + lnb[c]);
    }
}

// ---------------- merged weight prep ----------------
__global__ void prep_kernel(const float* __restrict__ wq, const float* __restrict__ wk,
                            const float* __restrict__ wv, const float* __restrict__ wo,
                            const float* __restrict__ w1, const float* __restrict__ w2,
                            const float* __restrict__ bq, const float* __restrict__ bk,
                            const float* __restrict__ bv,
                            unsigned short* __restrict__ owqkv, unsigned short* __restrict__ owo,
                            unsigned short* __restrict__ ow1, unsigned short* __restrict__ ow2,
                            float* __restrict__ obqkv) {
    int bid = blockIdx.x;
    if (bid >= 12288) {
        int i = (bid - 12288) * 256 + threadIdx.y * 32 + threadIdx.x;
        if (i < DIM) obqkv[i] = bq[i];
        else if (i < 2 * DIM) obqkv[i] = bk[i - DIM];
        else obqkv[i] = bv[i - 2 * DIM];
        return;
    }
    const float* in;
    unsigned short* out;
    int R, C, l;
    if (bid < 4096) {
        l = bid & 1023;
        R = DIM; C = DIM;
        int m = bid >> 10;
        in  = (m == 0) ? wq : (m == 1) ? wk : (m == 2) ? wv : wo;
        out = (m == 3) ? owo : owqkv + (size_t)m * DIM * DIM;
    } else if (bid < 8192) {
        l = bid - 4096; R = DIM; C = MLPD; in = w1; out = ow1;
    } else {
        l = bid - 8192; R = MLPD; C = DIM; in = w2; out = ow2;
    }
    int nbx = C >> 5;
    int bx = l % nbx, by = l / nbx;
    __shared__ float t[32][33];
    int c0 = bx * 32, r0 = by * 32;
    #pragma unroll
    for (int u = 0; u < 4; u++) {
        int r = r0 + threadIdx.y + u * 8;
        t[threadIdx.y + u * 8][threadIdx.x] = in[(size_t)r * C + c0 + threadIdx.x];
    }
    __syncthreads();
    #pragma unroll
    for (int u = 0; u < 4; u++) {
        int c = c0 + threadIdx.y + u * 8;
        out[(size_t)c * R + r0 + threadIdx.x] = f2h(t[threadIdx.x][threadIdx.y + u * 8]);
    }
}

// ---------------- fp16 GEMM 128x128 (double-barrier), optional split-K ----------------
// qscale: multiply output by 0.125 for columns < DIM (exact pow2, for attention scores)
#define TILEB 10240u
#define STAGES 4
#define GEMM_SMEM (STAGES * 2 * 10240)

__global__ __launch_bounds__(256, 2)
void gemm_mma_kernel(const unsigned short* __restrict__ A, const unsigned short* __restrict__ B,
                     const float* __restrict__ bias, const float* __restrict__ res,
                     float* __restrict__ outF, unsigned short* __restrict__ outH,
                     float* __restrict__ outP,
                     int N, int K, int ld, int gelu, int qscale) {
    extern __shared__ char smem[];
    const uint32_t sb = smem_u32(smem);
    const int tid  = threadIdx.x;
    const int wid  = tid >> 5;
    const int lane = tid & 31;
    const int wm = wid >> 2;
    const int wn = wid & 3;
    const int bm = blockIdx.y * 128;
    const int bn = blockIdx.x * 128;
    const int g  = lane >> 2;
    const int t4 = lane & 3;

    const unsigned short* Az = A + (size_t)blockIdx.z * K;
    const unsigned short* Bz = B + (size_t)blockIdx.z * K;

    const uint32_t aOff = (uint32_t)((((lane >> 3) & 1) * 8 + (lane & 7)) * 80 + (lane >> 4) * 16);
    const uint32_t bOff = (uint32_t)(((lane >> 4) * 8 + (lane & 7)) * 80 + ((lane >> 3) & 1) * 16);

    float acc[4][4][4];
    #pragma unroll
    for (int i = 0; i < 4; i++)
        #pragma unroll
        for (int j = 0; j < 4; j++)
            #pragma unroll
            for (int q = 0; q < 4; q++) acc[i][j][q] = 0.f;

    const int NCH = K >> 5;
    const unsigned short* gsrc[2] = {Az, Bz};
    const int rbase[2] = {bm, bn};

    auto load_chunk = [&](int stage, int k0) {
        #pragma unroll
        for (int t = 0; t < 2; t++) {
            uint32_t dst = sb + (uint32_t)(stage * 2 + t) * TILEB;
            const unsigned short* gp = gsrc[t];
            #pragma unroll
            for (int u = 0; u < 2; u++) {
                int idx = tid + 256 * u;
                int r = idx >> 2;
                int cc = idx & 3;
                cp_async16(dst + (uint32_t)(r * 80 + cc * 16),
                           gp + (size_t)(rbase[t] + r) * ld + k0 + cc * 8);
            }
        }
        CP_COMMIT();
    };

    #pragma unroll
    for (int s = 0; s < STAGES; s++) load_chunk(s, s * 32);

    int st = 0;
    for (int i = 0; i < NCH; i++) {
        CP_WAIT(STAGES - 1);
        __syncthreads();

        const uint32_t aB = sb + (uint32_t)(st * 2) * TILEB;
        const uint32_t bB = aB + TILEB;

        #pragma unroll
        for (int ks = 0; ks < 2; ks++) {
            uint32_t bf[2][4];
            #pragma unroll
            for (int np = 0; np < 2; np++) {
                uint32_t o = (uint32_t)((wn * 32 + np * 16) * 80 + ks * 32) + bOff;
                LDSM4(bf[np], bB + o);
            }
            #pragma unroll
            for (int mt = 0; mt < 4; mt++) {
                uint32_t af[4];
                uint32_t o = (uint32_t)((wm * 64 + mt * 16) * 80 + ks * 32) + aOff;
                LDSM4(af, aB + o);
                #pragma unroll
                for (int nt = 0; nt < 4; nt++) {
                    int np = nt >> 1, sub = (nt & 1) * 2;
                    MMA_F16(acc[mt][nt], af, bf[np][sub], bf[np][sub + 1]);
                }
            }
        }
        __syncthreads();

        if (i + STAGES < NCH) load_chunk(st, (i + STAGES) * 32);
        else                  CP_COMMIT();
        st = (st + 1) & (STAGES - 1);
    }

    if (outP) {
        float* po = outP + (size_t)blockIdx.z * SQ * N;
        #pragma unroll
        for (int mt = 0; mt < 4; mt++) {
            int r0 = bm + wm * 64 + mt * 16 + g;
            #pragma unroll
            for (int nt = 0; nt < 4; nt++) {
                int c = bn + wn * 32 + nt * 8 + t4 * 2;
                *(float2*)(po + (size_t)r0 * N + c)       = make_float2(acc[mt][nt][0], acc[mt][nt][1]);
                *(float2*)(po + (size_t)(r0 + 8) * N + c) = make_float2(acc[mt][nt][2], acc[mt][nt][3]);
            }
        }
        return;
    }

    #pragma unroll
    for (int mt = 0; mt < 4; mt++) {
        int r0 = bm + wm * 64 + mt * 16 + g;
        #pragma unroll
        for (int nt = 0; nt < 4; nt++) {
            int c = bn + wn * 32 + nt * 8 + t4 * 2;
            float v[4];
            v[0] = acc[mt][nt][0] + bias[c];
            v[1] = acc[mt][nt][1] + bias[c + 1];
            v[2] = acc[mt][nt][2] + bias[c];
            v[3] = acc[mt][nt][3] + bias[c + 1];
            if (gelu) {
                #pragma unroll
                for (int q = 0; q < 4; q++)
                    v[q] = 0.5f * v[q] * (1.0f + erff(v[q] * 0.70710678118654752f));
            }
            if (qscale) {
                // scale q columns (c < DIM) by 1/8 — exact power of two
                if (c < DIM)     { v[0] *= 0.125f; v[2] *= 0.125f; }
                if (c + 1 < DIM) { v[1] *= 0.125f; v[3] *= 0.125f; }
            }
            if (res) {
                v[0] += res[(size_t)r0 * N + c];
                v[1] += res[(size_t)r0 * N + c + 1];
                v[2] += res[(size_t)(r0 + 8) * N + c];
                v[3] += res[(size_t)(r0 + 8) * N + c + 1];
            }
            if (outF) {
                *(float2*)(outF + (size_t)r0 * N + c)       = make_float2(v[0], v[1]);
                *(float2*)(outF + (size_t)(r0 + 8) * N + c) = make_float2(v[2], v[3]);
            } else {
                *(uint32_t*)(outH + (size_t)r0 * N + c)       = pack2_h(v[0], v[1]);
                *(uint32_t*)(outH + (size_t)(r0 + 8) * N + c) = pack2_h(v[2], v[3]);
            }
        }
    }
}

// ---------------- split-K reduce (FFN2): out = p0 + p1 + bias + res ----------------
__global__ void reduce2_kernel(const float* __restrict__ p0, const float* __restrict__ p1,
                               const float* __restrict__ bias, const float* __restrict__ res,
                               float* __restrict__ out) {
    size_t i = ((size_t)blockIdx.x * 256 + threadIdx.x) * 4;
    int c = (int)(i & (DIM - 1));
    float4 a = *(const float4*)(p0 + i);
    float4 b = *(const float4*)(p1 + i);
    float4 r = *(const float4*)(res + i);
    float4 o;
    o.x = a.x + b.x + bias[c]     + r.x;
    o.y = a.y + b.y + bias[c + 1] + r.y;
    o.z = a.z + b.z + bias[c + 2] + r.z;
    o.w = a.w + b.w + bias[c + 3] + r.w;
    *(float4*)(out + i) = o;
}

// ---------------- flash attention (R9 geometry; q pre-scaled) ----------------
#define ATILE 9216u
#define ATT_SMEM (2 * 2 * 9216)

__global__ __launch_bounds__(128)
void attn_mma_kernel(const unsigned short* __restrict__ qkv,
                     unsigned short* __restrict__ O) {
    extern __shared__ char smem[];
    const uint32_t sb = smem_u32(smem);
    const int h  = blockIdx.y;
    const int q0 = blockIdx.x * 64;
    const int tid = threadIdx.x;
    const int w = tid >> 5, lane = tid & 31;
    const int g = lane >> 2, t4 = lane & 3;
    const int qcol = h * HDK, kcol = DIM + h * HDK, vcol = 2 * DIM + h * HDK;

    const uint32_t aOff = (uint32_t)((((lane >> 3) & 1) * 8 + (lane & 7)) * 144 + (lane >> 4) * 16);
    const uint32_t bOff = (uint32_t)(((lane >> 4) * 8 + (lane & 7)) * 144 + ((lane >> 3) & 1) * 16);
    const uint32_t vOff = (uint32_t)((lane & 15) * 144 + (lane >> 4) * 16);

    #define AK(s) (sb + (uint32_t)(s) * 2u * ATILE)
    #define AV(s) (AK(s) + ATILE)

    #pragma unroll
    for (int u = 0; u < 4; u++) {
        int idx = tid + u * 128;
        int row = idx >> 3, c16 = idx & 7;
        cp_async16(AK(0) + (uint32_t)(row * 144 + c16 * 16),
                   qkv + (size_t)(q0 + row) * QKVN + qcol + c16 * 8);
    }
    CP_COMMIT(); CP_WAIT(0); __syncthreads();

    uint32_t qh[4][4];
    #pragma unroll
    for (int ks = 0; ks < 4; ks++) {
        uint32_t o = (uint32_t)(w * 16 * 144 + ks * 32);
        LDSM4(qh[ks], AK(0) + o + aOff);
    }
    __syncthreads();

    auto load_kv = [&](int st, int kt) {
        #pragma unroll
        for (int u = 0; u < 4; u++) {
            int idx = tid + u * 128;
            int row = idx >> 3, c16 = idx & 7;
            uint32_t off = (uint32_t)(row * 144 + c16 * 16);
            cp_async16(AK(st) + off, qkv + (size_t)(kt + row) * QKVN + kcol + c16 * 8);
            cp_async16(AV(st) + off, qkv + (size_t)(kt + row) * QKVN + vcol + c16 * 8);
        }
        CP_COMMIT();
    };
    load_kv(0, 0);
    load_kv(1, 64);

    float of[8][4];
    #pragma unroll
    for (int j = 0; j < 8; j++)
        #pragma unroll
        for (int q = 0; q < 4; q++) of[j][q] = 0.f;
    float m0 = -1e30f, m1 = -1e30f, l0 = 0.f, l1 = 0.f;

    for (int it = 0; it < SQ / 64; it++) {
        CP_WAIT(1);
        __syncthreads();
        const int st = it & 1;

        float sf[8][4];
        #pragma unroll
        for (int j = 0; j < 8; j++)
            #pragma unroll
            for (int q = 0; q < 4; q++) sf[j][q] = 0.f;

        #pragma unroll
        for (int ks = 0; ks < 4; ks++) {
            #pragma unroll
            for (int nb = 0; nb < 4; nb++) {
                uint32_t kf[4];
                LDSM4(kf, AK(st) + (uint32_t)(nb * 16 * 144 + ks * 32) + bOff);
                MMA_F16(sf[2*nb],   qh[ks], kf[0], kf[1]);
                MMA_F16(sf[2*nb+1], qh[ks], kf[2], kf[3]);
            }
        }

        // scores already scaled by 1/8 (q pre-scaled in QKV epilogue)
        float mx0 = -1e30f, mx1 = -1e30f;
        #pragma unroll
        for (int j = 0; j < 8; j++) {
            mx0 = fmaxf(mx0, fmaxf(sf[j][0], sf[j][1]));
            mx1 = fmaxf(mx1, fmaxf(sf[j][2], sf[j][3]));
        }
        mx0 = fmaxf(mx0, __shfl_xor_sync(0xffffffffu, mx0, 1));
        mx0 = fmaxf(mx0, __shfl_xor_sync(0xffffffffu, mx0, 2));
        mx1 = fmaxf(mx1, __shfl_xor_sync(0xffffffffu, mx1, 1));
        mx1 = fmaxf(mx1, __shfl_xor_sync(0xffffffffu, mx1, 2));
        float mn0 = fmaxf(m0, mx0), mn1 = fmaxf(m1, mx1);
        float sc0 = __expf(m0 - mn0), sc1 = __expf(m1 - mn1);
        m0 = mn0; m1 = mn1;
        float s0 = 0.f, s1 = 0.f;
        #pragma unroll
        for (int j = 0; j < 8; j++) {
            sf[j][0] = __expf(sf[j][0] - mn0); s0 += sf[j][0];
            sf[j][1] = __expf(sf[j][1] - mn0); s0 += sf[j][1];
            sf[j][2] = __expf(sf[j][2] - mn1); s1 += sf[j][2];
            sf[j][3] = __expf(sf[j][3] - mn1); s1 += sf[j][3];
        }
        s0 += __shfl_xor_sync(0xffffffffu, s0, 1);
        s0 += __shfl_xor_sync(0xffffffffu, s0, 2);
        s1 += __shfl_xor_sync(0xffffffffu, s1, 1);
        s1 += __shfl_xor_sync(0xffffffffu, s1, 2);
        l0 = l0 * sc0 + s0;
        l1 = l1 * sc1 + s1;
        #pragma unroll
        for (int j = 0; j < 8; j++) {
            of[j][0] *= sc0; of[j][1] *= sc0;
            of[j][2] *= sc1; of[j][3] *= sc1;
        }

        #pragma unroll
        for (int jp = 0; jp < 4; jp++) {
            uint32_t p0 = pack2_h(sf[2*jp][0],   sf[2*jp][1]);
            uint32_t p1 = pack2_h(sf[2*jp][2],   sf[2*jp][3]);
            uint32_t p2 = pack2_h(sf[2*jp+1][0], sf[2*jp+1][1]);
            uint32_t p3 = pack2_h(sf[2*jp+1][2], sf[2*jp+1][3]);
            #pragma unroll
            for (int nb = 0; nb < 4; nb++) {
                uint32_t vf[4];
                LDSM4T(vf, AV(st) + (uint32_t)(jp * 16 * 144 + nb * 16 * 2) + vOff);
                MMA_F16R(of[2*nb],   p0, p1, p2, p3, vf[0], vf[1]);
                MMA_F16R(of[2*nb+1], p0, p1, p2, p3, vf[2], vf[3]);
            }
        }

        __syncthreads();
        if (it + 2 < SQ / 64) load_kv(st, (it + 2) * 64);
        else                  CP_COMMIT();
    }

    float inv0 = 1.0f / l0, inv1 = 1.0f / l1;
    int r0 = q0 + w * 16 + g;
    #pragma unroll
    for (int j = 0; j < 8; j++) {
        int d = 8 * j + 2 * t4;
        *(uint32_t*)(O + (size_t)h * SQ * HDK + (size_t)r0 * HDK + d) =
            pack2_h(of[j][0] * inv0, of[j][1] * inv0);
        *(uint32_t*)(O + (size_t)h * SQ * HDK + (size_t)(r0 + 8) * HDK + d) =
            pack2_h(of[j][2] * inv1, of[j][3] * inv1);
    }
}

// ---------------- launch ----------------
extern "C" void kernel_launch(void* const* d_in, const int* in_sizes, int n_in,
                              void* d_out, int out_size) {
    const float* x     = (const float*)d_in[0];
    const float* wq    = (const float*)d_in[1];
    const float* bq    = (const float*)d_in[2];
    const float* wk    = (const float*)d_in[3];
    const float* bk    = (const float*)d_in[4];
    const float* wv    = (const float*)d_in[5];
    const float* bv    = (const float*)d_in[6];
    const float* wo    = (const float*)d_in[7];
    const float* bo    = (const float*)d_in[8];
    const float* w1    = (const float*)d_in[9];
    const float* b1    = (const float*)d_in[10];
    const float* w2    = (const float*)d_in[11];
    const float* b2    = (const float*)d_in[12];
    const float* ln1_g = (const float*)d_in[13];
    const float* ln1_b = (const float*)d_in[14];
    const float* ln2_g = (const float*)d_in[15];
    const float* ln2_b = (const float*)d_in[16];
    float* out = (float*)d_out;

    unsigned short *hh, *qkv, *ao, *f, *wqkvh, *woh, *w1h, *w2h;
    float *x1, *bqkv, *part;
    cudaGetSymbolAddress((void**)&hh,   g_h);
    cudaGetSymbolAddress((void**)&qkv,  g_qkv);
    cudaGetSymbolAddress((void**)&ao,   g_ao);
    cudaGetSymbolAddress((void**)&x1,   g_x1);
    cudaGetSymbolAddress((void**)&f,    g_f);
    cudaGetSymbolAddress((void**)&wqkvh, g_wqkv);
    cudaGetSymbolAddress((void**)&woh,  g_wo);
    cudaGetSymbolAddress((void**)&w1h,  g_w1);
    cudaGetSymbolAddress((void**)&w2h,  g_w2);
    cudaGetSymbolAddress((void**)&bqkv, g_bqkv);
    cudaGetSymbolAddress((void**)&part, g_part);

    cudaFuncSetAttribute(gemm_mma_kernel,
                         cudaFuncAttributeMaxDynamicSharedMemorySize, GEMM_SMEM);
    cudaFuncSetAttribute(attn_mma_kernel,
                         cudaFuncAttributeMaxDynamicSharedMemorySize, ATT_SMEM);

    // prep
    ln_h_kernel<<<SQ, 256>>>(x, ln1_g, ln1_b, hh);
    prep_kernel<<<12300, dim3(32, 8)>>>(wq, wk, wv, wo, w1, w2, bq, bk, bv,
                                        wqkvh, woh, w1h, w2h, bqkv);
    // QKV fused GEMM -> fp16 (q columns pre-scaled by 1/8)
    gemm_mma_kernel<<<dim3(QKVN/128, SQ/128), 256, GEMM_SMEM>>>(
        hh, wqkvh, bqkv, nullptr, nullptr, qkv, nullptr, QKVN, DIM, DIM, 0, 1);
    // attention -> ao fp16
    attn_mma_kernel<<<dim3(SQ/64, NH), 128, ATT_SMEM>>>(qkv, ao);
    // O-proj split-K=2 -> partials
    gemm_mma_kernel<<<dim3(DIM/128, SQ/128, 2), 256, GEMM_SMEM>>>(
        ao, woh, nullptr, nullptr, nullptr, nullptr, part, DIM, DIM/2, DIM, 0, 0);
    // fused reduce + bias + residual(x) + LN2 -> x1 (fp32), hh (fp16)
    reduce_ln_kernel<<<SQ, 256>>>(part, part + (size_t)SQ * DIM, bo, x,
                                  ln2_g, ln2_b, x1, hh);
    // FFN1 + GELU -> f fp16
    gemm_mma_kernel<<<dim3(MLPD/128, SQ/128), 256, GEMM_SMEM>>>(
        hh, w1h, b1, nullptr, nullptr, f, nullptr, MLPD, DIM, DIM, 1, 0);
    // FFN2 split-K=2 -> partials, then reduce(+bias+residual) -> out
    gemm_mma_kernel<<<dim3(DIM/128, SQ/128, 2), 256, GEMM_SMEM>>>(
        f, w2h, nullptr, nullptr, nullptr, nullptr, part, DIM, MLPD/2, MLPD, 0, 0);
    reduce2_kernel<<<SQ * DIM / 1024, 256>>>(part, part + (size_t)SQ * DIM, b2, x1, out);
}

// round 13
// speedup vs baseline: 1.6105x; 1.0087x over previous
#include <cuda_runtime.h>
#include <cuda_fp16.h>
#include <math.h>
#include <stdint.h>

#define SQ   2048
#define DIM  1024
#define NH   16
#define HDK  64
#define MLPD 4096
#define QKVN 3072
#define NHSQ (NH * SQ)

// ---------------- scratch (no allocations allowed) ----------------
__device__ unsigned short g_h   [SQ*DIM];
__device__ unsigned short g_qkv [SQ*QKVN];
__device__ unsigned short g_ao  [SQ*DIM];
__device__ float          g_x1  [SQ*DIM];
__device__ unsigned short g_f   [SQ*MLPD];
__device__ unsigned short g_wqkv[QKVN*DIM];
__device__ unsigned short g_wo  [DIM*DIM];
__device__ unsigned short g_w1  [MLPD*DIM];
__device__ unsigned short g_w2  [DIM*MLPD];
__device__ float          g_bqkv[QKVN];
__device__ float          g_part[2][SQ*DIM];   // split-K / split-KV partials
__device__ float          g_ml  [4][NHSQ];     // [z*2+{m,l}][row]

// ---------------- helpers ----------------
__device__ __forceinline__ uint32_t smem_u32(const void* p) {
    uint32_t a;
    asm("{ .reg .u64 t; cvta.to.shared.u64 t, %1; cvt.u32.u64 %0, t; }" : "=r"(a) : "l"(p));
    return a;
}

__device__ __forceinline__ void cp_async16(uint32_t sdst, const void* gsrc) {
    asm volatile("cp.async.cg.shared.global [%0], [%1], 16;" :: "r"(sdst), "l"(gsrc) : "memory");
}
#define CP_COMMIT() asm volatile("cp.async.commit_group;" ::: "memory")
#define CP_WAIT(n)  asm volatile("cp.async.wait_group %0;" :: "n"(n) : "memory")

#define LDSM4(r, addr) \
    asm volatile("ldmatrix.sync.aligned.m8n8.x4.shared.b16 {%0,%1,%2,%3}, [%4];" \
        : "=r"((r)[0]), "=r"((r)[1]), "=r"((r)[2]), "=r"((r)[3]) : "r"(addr))

#define LDSM4T(r, addr) \
    asm volatile("ldmatrix.sync.aligned.m8n8.x4.trans.shared.b16 {%0,%1,%2,%3}, [%4];" \
        : "=r"((r)[0]), "=r"((r)[1]), "=r"((r)[2]), "=r"((r)[3]) : "r"(addr))

#define MMA_F16(c, a, b0, b1) \
    asm volatile("mma.sync.aligned.m16n8k16.row.col.f32.f16.f16.f32 " \
        "{%0,%1,%2,%3}, {%4,%5,%6,%7}, {%8,%9}, {%0,%1,%2,%3};" \
        : "+f"((c)[0]), "+f"((c)[1]), "+f"((c)[2]), "+f"((c)[3]) \
        : "r"((a)[0]), "r"((a)[1]), "r"((a)[2]), "r"((a)[3]), "r"(b0), "r"(b1))

#define MMA_F16R(c, a0, a1, a2, a3, b0, b1) \
    asm volatile("mma.sync.aligned.m16n8k16.row.col.f32.f16.f16.f32 " \
        "{%0,%1,%2,%3}, {%4,%5,%6,%7}, {%8,%9}, {%0,%1,%2,%3};" \
        : "+f"((c)[0]), "+f"((c)[1]), "+f"((c)[2]), "+f"((c)[3]) \
        : "r"(a0), "r"(a1), "r"(a2), "r"(a3), "r"(b0), "r"(b1))

__device__ __forceinline__ unsigned short f2h(float v) {
    return __half_as_ushort(__float2half_rn(v));
}
__device__ __forceinline__ uint32_t pack2_h(float a, float b) {
    __half2 h = __floats2half2_rn(a, b);
    return *(uint32_t*)&h;
}

// ---------------- shared reduction (flat tid) ----------------
__device__ __forceinline__ float block_sum_256(float v, float* sh, int t) {
    int lane = t & 31, w = t >> 5;
    #pragma unroll
    for (int o = 16; o; o >>= 1) v += __shfl_xor_sync(0xffffffffu, v, o);
    __syncthreads();
    if (lane == 0) sh[w] = v;
    __syncthreads();
    float r = 0.f;
    #pragma unroll
    for (int i = 0; i < 8; i++) r += sh[i];
    return r;
}

// ---------------- fused split-K reduce + residual + LN2 ----------------
__global__ void reduce_ln_kernel(const float* __restrict__ p0, const float* __restrict__ p1,
                                 const float* __restrict__ bias, const float* __restrict__ res,
                                 const float* __restrict__ lng, const float* __restrict__ lnb,
                                 float* __restrict__ x1, unsigned short* __restrict__ oh) {
    __shared__ float sh[8];
    int row = blockIdx.x;
    int t = threadIdx.x;
    size_t base = (size_t)row * DIM;
    float v0[4];
    float s = 0.f;
    #pragma unroll
    for (int u = 0; u < 4; u++) {
        int c = t + u * 256;
        float v = p0[base + c] + p1[base + c] + bias[c] + res[base + c];
        v0[u] = v; s += v;
        x1[base + c] = v;
    }
    s = block_sum_256(s, sh, t);
    float mean = s * (1.0f / DIM);
    float vs = 0.f;
    #pragma unroll
    for (int u = 0; u < 4; u++) { float d = v0[u] - mean; vs += d * d; }
    vs = block_sum_256(vs, sh, t);
    float rstd = rsqrtf(vs * (1.0f / DIM) + 1e-5f);
    #pragma unroll
    for (int u = 0; u < 4; u++) {
        int c = t + u * 256;
        oh[base + c] = f2h((v0[u] - mean) * rstd * lng[c] + lnb[c]);
    }
}

// ---------------- merged prep: weight transposes + bias concat + LN1 ----------------
// [0,4096) wq/wk/wv/wo | [4096,8192) w1 | [8192,12288) w2 | [12288,12300) bias |
// [12300,14348) LN1 rows
__global__ void prep_kernel(const float* __restrict__ wq, const float* __restrict__ wk,
                            const float* __restrict__ wv, const float* __restrict__ wo,
                            const float* __restrict__ w1, const float* __restrict__ w2,
                            const float* __restrict__ bq, const float* __restrict__ bk,
                            const float* __restrict__ bv,
                            const float* __restrict__ x, const float* __restrict__ ln1g,
                            const float* __restrict__ ln1b,
                            unsigned short* __restrict__ owqkv, unsigned short* __restrict__ owo,
                            unsigned short* __restrict__ ow1, unsigned short* __restrict__ ow2,
                            float* __restrict__ obqkv, unsigned short* __restrict__ oh) {
    int bid = blockIdx.x;
    int t = threadIdx.y * 32 + threadIdx.x;
    if (bid >= 12300) {
        // LN1 row
        __shared__ float sh[8];
        int row = bid - 12300;
        size_t base = (size_t)row * DIM;
        float v0[4];
        float s = 0.f;
        #pragma unroll
        for (int u = 0; u < 4; u++) { v0[u] = x[base + t + u * 256]; s += v0[u]; }
        s = block_sum_256(s, sh, t);
        float mean = s * (1.0f / DIM);
        float vs = 0.f;
        #pragma unroll
        for (int u = 0; u < 4; u++) { float d = v0[u] - mean; vs += d * d; }
        vs = block_sum_256(vs, sh, t);
        float rstd = rsqrtf(vs * (1.0f / DIM) + 1e-5f);
        #pragma unroll
        for (int u = 0; u < 4; u++) {
            int c = t + u * 256;
            oh[base + c] = f2h((v0[u] - mean) * rstd * ln1g[c] + ln1b[c]);
        }
        return;
    }
    if (bid >= 12288) {
        int i = (bid - 12288) * 256 + t;
        if (i < DIM) obqkv[i] = bq[i];
        else if (i < 2 * DIM) obqkv[i] = bk[i - DIM];
        else obqkv[i] = bv[i - 2 * DIM];
        return;
    }
    const float* in;
    unsigned short* out;
    int R, C, l;
    if (bid < 4096) {
        l = bid & 1023;
        R = DIM; C = DIM;
        int m = bid >> 10;
        in  = (m == 0) ? wq : (m == 1) ? wk : (m == 2) ? wv : wo;
        out = (m == 3) ? owo : owqkv + (size_t)m * DIM * DIM;
    } else if (bid < 8192) {
        l = bid - 4096; R = DIM; C = MLPD; in = w1; out = ow1;
    } else {
        l = bid - 8192; R = MLPD; C = DIM; in = w2; out = ow2;
    }
    int nbx = C >> 5;
    int bx = l % nbx, by = l / nbx;
    __shared__ float tt[32][33];
    int c0 = bx * 32, r0 = by * 32;
    #pragma unroll
    for (int u = 0; u < 4; u++) {
        int r = r0 + threadIdx.y + u * 8;
        tt[threadIdx.y + u * 8][threadIdx.x] = in[(size_t)r * C + c0 + threadIdx.x];
    }
    __syncthreads();
    #pragma unroll
    for (int u = 0; u < 4; u++) {
        int c = c0 + threadIdx.y + u * 8;
        out[(size_t)c * R + r0 + threadIdx.x] = f2h(tt[threadIdx.x][threadIdx.y + u * 8]);
    }
}

// ---------------- fp16 GEMM 128x128 (double-barrier), optional split-K ----------------
// qscale: scale columns < DIM by 0.125*log2(e) (attention score prep, exp2 domain)
#define TILEB 10240u
#define STAGES 4
#define GEMM_SMEM (STAGES * 2 * 10240)
#define QSCALE_F 0.1803368801111204f   // 0.125 * log2(e)

__global__ __launch_bounds__(256, 2)
void gemm_mma_kernel(const unsigned short* __restrict__ A, const unsigned short* __restrict__ B,
                     const float* __restrict__ bias, const float* __restrict__ res,
                     float* __restrict__ outF, unsigned short* __restrict__ outH,
                     float* __restrict__ outP,
                     int N, int K, int ld, int gelu, int qscale) {
    extern __shared__ char smem[];
    const uint32_t sb = smem_u32(smem);
    const int tid  = threadIdx.x;
    const int wid  = tid >> 5;
    const int lane = tid & 31;
    const int wm = wid >> 2;
    const int wn = wid & 3;
    const int bm = blockIdx.y * 128;
    const int bn = blockIdx.x * 128;
    const int g  = lane >> 2;
    const int t4 = lane & 3;

    const unsigned short* Az = A + (size_t)blockIdx.z * K;
    const unsigned short* Bz = B + (size_t)blockIdx.z * K;

    const uint32_t aOff = (uint32_t)((((lane >> 3) & 1) * 8 + (lane & 7)) * 80 + (lane >> 4) * 16);
    const uint32_t bOff = (uint32_t)(((lane >> 4) * 8 + (lane & 7)) * 80 + ((lane >> 3) & 1) * 16);

    float acc[4][4][4];
    #pragma unroll
    for (int i = 0; i < 4; i++)
        #pragma unroll
        for (int j = 0; j < 4; j++)
            #pragma unroll
            for (int q = 0; q < 4; q++) acc[i][j][q] = 0.f;

    const int NCH = K >> 5;
    const unsigned short* gsrc[2] = {Az, Bz};
    const int rbase[2] = {bm, bn};

    auto load_chunk = [&](int stage, int k0) {
        #pragma unroll
        for (int t = 0; t < 2; t++) {
            uint32_t dst = sb + (uint32_t)(stage * 2 + t) * TILEB;
            const unsigned short* gp = gsrc[t];
            #pragma unroll
            for (int u = 0; u < 2; u++) {
                int idx = tid + 256 * u;
                int r = idx >> 2;
                int cc = idx & 3;
                cp_async16(dst + (uint32_t)(r * 80 + cc * 16),
                           gp + (size_t)(rbase[t] + r) * ld + k0 + cc * 8);
            }
        }
        CP_COMMIT();
    };

    #pragma unroll
    for (int s = 0; s < STAGES; s++) load_chunk(s, s * 32);

    int st = 0;
    for (int i = 0; i < NCH; i++) {
        CP_WAIT(STAGES - 1);
        __syncthreads();

        const uint32_t aB = sb + (uint32_t)(st * 2) * TILEB;
        const uint32_t bB = aB + TILEB;

        #pragma unroll
        for (int ks = 0; ks < 2; ks++) {
            uint32_t bf[2][4];
            #pragma unroll
            for (int np = 0; np < 2; np++) {
                uint32_t o = (uint32_t)((wn * 32 + np * 16) * 80 + ks * 32) + bOff;
                LDSM4(bf[np], bB + o);
            }
            #pragma unroll
            for (int mt = 0; mt < 4; mt++) {
                uint32_t af[4];
                uint32_t o = (uint32_t)((wm * 64 + mt * 16) * 80 + ks * 32) + aOff;
                LDSM4(af, aB + o);
                #pragma unroll
                for (int nt = 0; nt < 4; nt++) {
                    int np = nt >> 1, sub = (nt & 1) * 2;
                    MMA_F16(acc[mt][nt], af, bf[np][sub], bf[np][sub + 1]);
                }
            }
        }
        __syncthreads();

        if (i + STAGES < NCH) load_chunk(st, (i + STAGES) * 32);
        else                  CP_COMMIT();
        st = (st + 1) & (STAGES - 1);
    }

    if (outP) {
        float* po = outP + (size_t)blockIdx.z * SQ * N;
        #pragma unroll
        for (int mt = 0; mt < 4; mt++) {
            int r0 = bm + wm * 64 + mt * 16 + g;
            #pragma unroll
            for (int nt = 0; nt < 4; nt++) {
                int c = bn + wn * 32 + nt * 8 + t4 * 2;
                *(float2*)(po + (size_t)r0 * N + c)       = make_float2(acc[mt][nt][0], acc[mt][nt][1]);
                *(float2*)(po + (size_t)(r0 + 8) * N + c) = make_float2(acc[mt][nt][2], acc[mt][nt][3]);
            }
        }
        return;
    }

    #pragma unroll
    for (int mt = 0; mt < 4; mt++) {
        int r0 = bm + wm * 64 + mt * 16 + g;
        #pragma unroll
        for (int nt = 0; nt < 4; nt++) {
            int c = bn + wn * 32 + nt * 8 + t4 * 2;
            float v[4];
            v[0] = acc[mt][nt][0] + bias[c];
            v[1] = acc[mt][nt][1] + bias[c + 1];
            v[2] = acc[mt][nt][2] + bias[c];
            v[3] = acc[mt][nt][3] + bias[c + 1];
            if (gelu) {
                #pragma unroll
                for (int q = 0; q < 4; q++)
                    v[q] = 0.5f * v[q] * (1.0f + erff(v[q] * 0.70710678118654752f));
            }
            if (qscale) {
                if (c < DIM)     { v[0] *= QSCALE_F; v[2] *= QSCALE_F; }
                if (c + 1 < DIM) { v[1] *= QSCALE_F; v[3] *= QSCALE_F; }
            }
            if (res) {
                v[0] += res[(size_t)r0 * N + c];
                v[1] += res[(size_t)r0 * N + c + 1];
                v[2] += res[(size_t)(r0 + 8) * N + c];
                v[3] += res[(size_t)(r0 + 8) * N + c + 1];
            }
            if (outF) {
                *(float2*)(outF + (size_t)r0 * N + c)       = make_float2(v[0], v[1]);
                *(float2*)(outF + (size_t)(r0 + 8) * N + c) = make_float2(v[2], v[3]);
            } else {
                *(uint32_t*)(outH + (size_t)r0 * N + c)       = pack2_h(v[0], v[1]);
                *(uint32_t*)(outH + (size_t)(r0 + 8) * N + c) = pack2_h(v[2], v[3]);
            }
        }
    }
}

// ---------------- split-K reduce (FFN2): out = p0 + p1 + bias + res ----------------
__global__ void reduce2_kernel(const float* __restrict__ p0, const float* __restrict__ p1,
                               const float* __restrict__ bias, const float* __restrict__ res,
                               float* __restrict__ out) {
    size_t i = ((size_t)blockIdx.x * 256 + threadIdx.x) * 4;
    int c = (int)(i & (DIM - 1));
    float4 a = *(const float4*)(p0 + i);
    float4 b = *(const float4*)(p1 + i);
    float4 r = *(const float4*)(res + i);
    float4 o;
    o.x = a.x + b.x + bias[c]     + r.x;
    o.y = a.y + b.y + bias[c + 1] + r.y;
    o.z = a.z + b.z + bias[c + 2] + r.z;
    o.w = a.w + b.w + bias[c + 3] + r.w;
    *(float4*)(out + i) = o;
}

// ---------------- flash attention, split-KV (z=2), exp2 domain ----------------
#define ATILE 9216u
#define ATT_SMEM (2 * 2 * 9216)

__global__ __launch_bounds__(128)
void attn_mma_kernel(const unsigned short* __restrict__ qkv,
                     float* __restrict__ partO, float* __restrict__ ml) {
    extern __shared__ char smem[];
    const uint32_t sb = smem_u32(smem);
    const int h  = blockIdx.y;
    const int q0 = blockIdx.x * 64;
    const int z  = blockIdx.z;
    const int kbase = z * (SQ / 2);
    const int tid = threadIdx.x;
    const int w = tid >> 5, lane = tid & 31;
    const int g = lane >> 2, t4 = lane & 3;
    const int qcol = h * HDK, kcol = DIM + h * HDK, vcol = 2 * DIM + h * HDK;

    const uint32_t aOff = (uint32_t)((((lane >> 3) & 1) * 8 + (lane & 7)) * 144 + (lane >> 4) * 16);
    const uint32_t bOff = (uint32_t)(((lane >> 4) * 8 + (lane & 7)) * 144 + ((lane >> 3) & 1) * 16);
    const uint32_t vOff = (uint32_t)((lane & 15) * 144 + (lane >> 4) * 16);

    #define AK(s) (sb + (uint32_t)(s) * 2u * ATILE)
    #define AV(s) (AK(s) + ATILE)

    #pragma unroll
    for (int u = 0; u < 4; u++) {
        int idx = tid + u * 128;
        int row = idx >> 3, c16 = idx & 7;
        cp_async16(AK(0) + (uint32_t)(row * 144 + c16 * 16),
                   qkv + (size_t)(q0 + row) * QKVN + qcol + c16 * 8);
    }
    CP_COMMIT(); CP_WAIT(0); __syncthreads();

    uint32_t qh[4][4];
    #pragma unroll
    for (int ks = 0; ks < 4; ks++) {
        uint32_t o = (uint32_t)(w * 16 * 144 + ks * 32);
        LDSM4(qh[ks], AK(0) + o + aOff);
    }
    __syncthreads();

    auto load_kv = [&](int st, int kt) {
        #pragma unroll
        for (int u = 0; u < 4; u++) {
            int idx = tid + u * 128;
            int row = idx >> 3, c16 = idx & 7;
            uint32_t off = (uint32_t)(row * 144 + c16 * 16);
            cp_async16(AK(st) + off, qkv + (size_t)(kt + row) * QKVN + kcol + c16 * 8);
            cp_async16(AV(st) + off, qkv + (size_t)(kt + row) * QKVN + vcol + c16 * 8);
        }
        CP_COMMIT();
    };
    load_kv(0, kbase);
    load_kv(1, kbase + 64);

    float of[8][4];
    #pragma unroll
    for (int j = 0; j < 8; j++)
        #pragma unroll
        for (int q = 0; q < 4; q++) of[j][q] = 0.f;
    float m0 = -1e30f, m1 = -1e30f, l0 = 0.f, l1 = 0.f;

    const int NIT = SQ / 128;   // 16 iterations per split
    for (int it = 0; it < NIT; it++) {
        CP_WAIT(1);
        __syncthreads();
        const int st = it & 1;

        float sf[8][4];
        #pragma unroll
        for (int j = 0; j < 8; j++)
            #pragma unroll
            for (int q = 0; q < 4; q++) sf[j][q] = 0.f;

        #pragma unroll
        for (int ks = 0; ks < 4; ks++) {
            #pragma unroll
            for (int nb = 0; nb < 4; nb++) {
                uint32_t kf[4];
                LDSM4(kf, AK(st) + (uint32_t)(nb * 16 * 144 + ks * 32) + bOff);
                MMA_F16(sf[2*nb],   qh[ks], kf[0], kf[1]);
                MMA_F16(sf[2*nb+1], qh[ks], kf[2], kf[3]);
            }
        }

        // scores in exp2 domain (q pre-scaled by 0.125*log2e)
        float mx0 = -1e30f, mx1 = -1e30f;
        #pragma unroll
        for (int j = 0; j < 8; j++) {
            mx0 = fmaxf(mx0, fmaxf(sf[j][0], sf[j][1]));
            mx1 = fmaxf(mx1, fmaxf(sf[j][2], sf[j][3]));
        }
        mx0 = fmaxf(mx0, __shfl_xor_sync(0xffffffffu, mx0, 1));
        mx0 = fmaxf(mx0, __shfl_xor_sync(0xffffffffu, mx0, 2));
        mx1 = fmaxf(mx1, __shfl_xor_sync(0xffffffffu, mx1, 1));
        mx1 = fmaxf(mx1, __shfl_xor_sync(0xffffffffu, mx1, 2));
        float mn0 = fmaxf(m0, mx0), mn1 = fmaxf(m1, mx1);
        float sc0 = exp2f(m0 - mn0), sc1 = exp2f(m1 - mn1);
        m0 = mn0; m1 = mn1;
        float s0 = 0.f, s1 = 0.f;
        #pragma unroll
        for (int j = 0; j < 8; j++) {
            sf[j][0] = exp2f(sf[j][0] - mn0); s0 += sf[j][0];
            sf[j][1] = exp2f(sf[j][1] - mn0); s0 += sf[j][1];
            sf[j][2] = exp2f(sf[j][2] - mn1); s1 += sf[j][2];
            sf[j][3] = exp2f(sf[j][3] - mn1); s1 += sf[j][3];
        }
        s0 += __shfl_xor_sync(0xffffffffu, s0, 1);
        s0 += __shfl_xor_sync(0xffffffffu, s0, 2);
        s1 += __shfl_xor_sync(0xffffffffu, s1, 1);
        s1 += __shfl_xor_sync(0xffffffffu, s1, 2);
        l0 = l0 * sc0 + s0;
        l1 = l1 * sc1 + s1;
        #pragma unroll
        for (int j = 0; j < 8; j++) {
            of[j][0] *= sc0; of[j][1] *= sc0;
            of[j][2] *= sc1; of[j][3] *= sc1;
        }

        #pragma unroll
        for (int jp = 0; jp < 4; jp++) {
            uint32_t p0 = pack2_h(sf[2*jp][0],   sf[2*jp][1]);
            uint32_t p1 = pack2_h(sf[2*jp][2],   sf[2*jp][3]);
            uint32_t p2 = pack2_h(sf[2*jp+1][0], sf[2*jp+1][1]);
            uint32_t p3 = pack2_h(sf[2*jp+1][2], sf[2*jp+1][3]);
            #pragma unroll
            for (int nb = 0; nb < 4; nb++) {
                uint32_t vf[4];
                LDSM4T(vf, AV(st) + (uint32_t)(jp * 16 * 144 + nb * 16 * 2) + vOff);
                MMA_F16R(of[2*nb],   p0, p1, p2, p3, vf[0], vf[1]);
                MMA_F16R(of[2*nb+1], p0, p1, p2, p3, vf[2], vf[3]);
            }
        }

        __syncthreads();
        if (it + 2 < NIT) load_kv(st, kbase + (it + 2) * 64);
        else              CP_COMMIT();
    }

    // write unnormalized partials + (m, l)
    float* po = partO + (size_t)z * SQ * DIM;
    float* mlz = ml + (size_t)z * 2 * NHSQ;
    int rg0 = h * SQ + q0 + w * 16 + g;
    if (t4 == 0) {
        mlz[rg0]            = m0;
        mlz[NHSQ + rg0]     = l0;
        mlz[rg0 + 8]        = m1;
        mlz[NHSQ + rg0 + 8] = l1;
    }
    #pragma unroll
    for (int j = 0; j < 8; j++) {
        int d = 8 * j + 2 * t4;
        *(float2*)(po + (size_t)rg0 * HDK + d)       = make_float2(of[j][0], of[j][1]);
        *(float2*)(po + (size_t)(rg0 + 8) * HDK + d) = make_float2(of[j][2], of[j][3]);
    }
}

// ---------------- split-KV merge -> ao fp16 ----------------
__global__ void attn_merge_kernel(const float* __restrict__ p0, const float* __restrict__ p1,
                                  const float* __restrict__ ml, unsigned short* __restrict__ O) {
    int idx = blockIdx.x * 256 + threadIdx.x;   // over NHSQ*HDK elements
    int r = idx >> 6;
    float m0 = ml[r],            l0 = ml[NHSQ + r];
    float m1 = ml[2 * NHSQ + r], l1 = ml[3 * NHSQ + r];
    float m = fmaxf(m0, m1);
    float w0 = exp2f(m0 - m), w1 = exp2f(m1 - m);
    float inv = 1.0f / (l0 * w0 + l1 * w1);
    O[idx] = f2h((p0[idx] * w0 + p1[idx] * w1) * inv);
}

// ---------------- launch ----------------
extern "C" void kernel_launch(void* const* d_in, const int* in_sizes, int n_in,
                              void* d_out, int out_size) {
    const float* x     = (const float*)d_in[0];
    const float* wq    = (const float*)d_in[1];
    const float* bq    = (const float*)d_in[2];
    const float* wk    = (const float*)d_in[3];
    const float* bk    = (const float*)d_in[4];
    const float* wv    = (const float*)d_in[5];
    const float* bv    = (const float*)d_in[6];
    const float* wo    = (const float*)d_in[7];
    const float* bo    = (const float*)d_in[8];
    const float* w1    = (const float*)d_in[9];
    const float* b1    = (const float*)d_in[10];
    const float* w2    = (const float*)d_in[11];
    const float* b2    = (const float*)d_in[12];
    const float* ln1_g = (const float*)d_in[13];
    const float* ln1_b = (const float*)d_in[14];
    const float* ln2_g = (const float*)d_in[15];
    const float* ln2_b = (const float*)d_in[16];
    float* out = (float*)d_out;

    unsigned short *hh, *qkv, *ao, *f, *wqkvh, *woh, *w1h, *w2h;
    float *x1, *bqkv, *part, *ml;
    cudaGetSymbolAddress((void**)&hh,   g_h);
    cudaGetSymbolAddress((void**)&qkv,  g_qkv);
    cudaGetSymbolAddress((void**)&ao,   g_ao);
    cudaGetSymbolAddress((void**)&x1,   g_x1);
    cudaGetSymbolAddress((void**)&f,    g_f);
    cudaGetSymbolAddress((void**)&wqkvh, g_wqkv);
    cudaGetSymbolAddress((void**)&woh,  g_wo);
    cudaGetSymbolAddress((void**)&w1h,  g_w1);
    cudaGetSymbolAddress((void**)&w2h,  g_w2);
    cudaGetSymbolAddress((void**)&bqkv, g_bqkv);
    cudaGetSymbolAddress((void**)&part, g_part);
    cudaGetSymbolAddress((void**)&ml,   g_ml);

    cudaFuncSetAttribute(gemm_mma_kernel,
                         cudaFuncAttributeMaxDynamicSharedMemorySize, GEMM_SMEM);
    cudaFuncSetAttribute(attn_mma_kernel,
                         cudaFuncAttributeMaxDynamicSharedMemorySize, ATT_SMEM);

    // prep: weights + bias + LN1 in one launch
    prep_kernel<<<14348, dim3(32, 8)>>>(wq, wk, wv, wo, w1, w2, bq, bk, bv,
                                        x, ln1_g, ln1_b,
                                        wqkvh, woh, w1h, w2h, bqkv, hh);
    // QKV fused GEMM -> fp16 (q pre-scaled by 0.125*log2e)
    gemm_mma_kernel<<<dim3(QKVN/128, SQ/128), 256, GEMM_SMEM>>>(
        hh, wqkvh, bqkv, nullptr, nullptr, qkv, nullptr, QKVN, DIM, DIM, 0, 1);
    // attention split-KV (z=2) -> partials, then merge -> ao fp16
    attn_mma_kernel<<<dim3(SQ/64, NH, 2), 128, ATT_SMEM>>>(qkv, part, ml);
    attn_merge_kernel<<<NHSQ * HDK / 256, 256>>>(part, part + (size_t)SQ * DIM, ml, ao);
    // O-proj split-K=2 -> partials
    gemm_mma_kernel<<<dim3(DIM/128, SQ/128, 2), 256, GEMM_SMEM>>>(
        ao, woh, nullptr, nullptr, nullptr, nullptr, part, DIM, DIM/2, DIM, 0, 0);
    // fused reduce + bias + residual(x) + LN2 -> x1, hh
    reduce_ln_kernel<<<SQ, 256>>>(part, part + (size_t)SQ * DIM, bo, x,
                                  ln2_g, ln2_b, x1, hh);
    // FFN1 + GELU -> f fp16
    gemm_mma_kernel<<<dim3(MLPD/128, SQ/128), 256, GEMM_SMEM>>>(
        hh, w1h, b1, nullptr, nullptr, f, nullptr, MLPD, DIM, DIM, 1, 0);
    // FFN2 split-K=2 -> partials, then reduce -> out
    gemm_mma_kernel<<<dim3(DIM/128, SQ/128, 2), 256, GEMM_SMEM>>>(
        f, w2h, nullptr, nullptr, nullptr, nullptr, part, DIM, MLPD/2, MLPD, 0, 0);
    reduce2_kernel<<<SQ * DIM / 1024, 256>>>(part, part + (size_t)SQ * DIM, b2, x1, out);
}

// round 14
// speedup vs baseline: 1.6308x; 1.0126x over previous
#include <cuda_runtime.h>
#include <cuda_fp16.h>
#include <math.h>
#include <stdint.h>

#define SQ   2048
#define DIM  1024
#define NH   16
#define HDK  64
#define MLPD 4096
#define QKVN 3072
#define NHSQ (NH * SQ)

// ---------------- scratch (no allocations allowed) ----------------
__device__ unsigned short g_h   [SQ*DIM];
__device__ unsigned short g_qkv [SQ*QKVN];
__device__ unsigned short g_ao  [SQ*DIM];
__device__ float          g_x1  [SQ*DIM];
__device__ unsigned short g_f   [SQ*MLPD];
__device__ unsigned short g_wqkv[QKVN*DIM];
__device__ unsigned short g_wo  [DIM*DIM];
__device__ unsigned short g_w1  [MLPD*DIM];
__device__ unsigned short g_w2  [DIM*MLPD];
__device__ float          g_bqkv[QKVN];
__device__ float          g_part[2][SQ*DIM];   // split-K / split-KV partials
__device__ float          g_ml  [4][NHSQ];     // [z*2+{m,l}][row]

// ---------------- helpers ----------------
__device__ __forceinline__ uint32_t smem_u32(const void* p) {
    uint32_t a;
    asm("{ .reg .u64 t; cvta.to.shared.u64 t, %1; cvt.u32.u64 %0, t; }" : "=r"(a) : "l"(p));
    return a;
}

__device__ __forceinline__ void cp_async16(uint32_t sdst, const void* gsrc) {
    asm volatile("cp.async.cg.shared.global [%0], [%1], 16;" :: "r"(sdst), "l"(gsrc) : "memory");
}
#define CP_COMMIT() asm volatile("cp.async.commit_group;" ::: "memory")
#define CP_WAIT(n)  asm volatile("cp.async.wait_group %0;" :: "n"(n) : "memory")

#define LDSM4(r, addr) \
    asm volatile("ldmatrix.sync.aligned.m8n8.x4.shared.b16 {%0,%1,%2,%3}, [%4];" \
        : "=r"((r)[0]), "=r"((r)[1]), "=r"((r)[2]), "=r"((r)[3]) : "r"(addr))

#define LDSM4T(r, addr) \
    asm volatile("ldmatrix.sync.aligned.m8n8.x4.trans.shared.b16 {%0,%1,%2,%3}, [%4];" \
        : "=r"((r)[0]), "=r"((r)[1]), "=r"((r)[2]), "=r"((r)[3]) : "r"(addr))

#define MMA_F16(c, a, b0, b1) \
    asm volatile("mma.sync.aligned.m16n8k16.row.col.f32.f16.f16.f32 " \
        "{%0,%1,%2,%3}, {%4,%5,%6,%7}, {%8,%9}, {%0,%1,%2,%3};" \
        : "+f"((c)[0]), "+f"((c)[1]), "+f"((c)[2]), "+f"((c)[3]) \
        : "r"((a)[0]), "r"((a)[1]), "r"((a)[2]), "r"((a)[3]), "r"(b0), "r"(b1))

#define MMA_F16R(c, a0, a1, a2, a3, b0, b1) \
    asm volatile("mma.sync.aligned.m16n8k16.row.col.f32.f16.f16.f32 " \
        "{%0,%1,%2,%3}, {%4,%5,%6,%7}, {%8,%9}, {%0,%1,%2,%3};" \
        : "+f"((c)[0]), "+f"((c)[1]), "+f"((c)[2]), "+f"((c)[3]) \
        : "r"(a0), "r"(a1), "r"(a2), "r"(a3), "r"(b0), "r"(b1))

__device__ __forceinline__ unsigned short f2h(float v) {
    return __half_as_ushort(__float2half_rn(v));
}
__device__ __forceinline__ uint32_t pack2_h(float a, float b) {
    __half2 h = __floats2half2_rn(a, b);
    return *(uint32_t*)&h;
}

// ---------------- shared reduction (flat tid) ----------------
__device__ __forceinline__ float block_sum_256(float v, float* sh, int t) {
    int lane = t & 31, w = t >> 5;
    #pragma unroll
    for (int o = 16; o; o >>= 1) v += __shfl_xor_sync(0xffffffffu, v, o);
    __syncthreads();
    if (lane == 0) sh[w] = v;
    __syncthreads();
    float r = 0.f;
    #pragma unroll
    for (int i = 0; i < 8; i++) r += sh[i];
    return r;
}

// ---------------- fused split-K reduce + residual + LN2 ----------------
__global__ void reduce_ln_kernel(const float* __restrict__ p0, const float* __restrict__ p1,
                                 const float* __restrict__ bias, const float* __restrict__ res,
                                 const float* __restrict__ lng, const float* __restrict__ lnb,
                                 float* __restrict__ x1, unsigned short* __restrict__ oh) {
    __shared__ float sh[8];
    int row = blockIdx.x;
    int t = threadIdx.x;
    size_t base = (size_t)row * DIM;
    float v0[4];
    float s = 0.f;
    #pragma unroll
    for (int u = 0; u < 4; u++) {
        int c = t + u * 256;
        float v = p0[base + c] + p1[base + c] + bias[c] + res[base + c];
        v0[u] = v; s += v;
        x1[base + c] = v;
    }
    s = block_sum_256(s, sh, t);
    float mean = s * (1.0f / DIM);
    float vs = 0.f;
    #pragma unroll
    for (int u = 0; u < 4; u++) { float d = v0[u] - mean; vs += d * d; }
    vs = block_sum_256(vs, sh, t);
    float rstd = rsqrtf(vs * (1.0f / DIM) + 1e-5f);
    #pragma unroll
    for (int u = 0; u < 4; u++) {
        int c = t + u * 256;
        oh[base + c] = f2h((v0[u] - mean) * rstd * lng[c] + lnb[c]);
    }
}

// ---------------- merged prep: weight transposes + bias concat + LN1 ----------------
__global__ void prep_kernel(const float* __restrict__ wq, const float* __restrict__ wk,
                            const float* __restrict__ wv, const float* __restrict__ wo,
                            const float* __restrict__ w1, const float* __restrict__ w2,
                            const float* __restrict__ bq, const float* __restrict__ bk,
                            const float* __restrict__ bv,
                            const float* __restrict__ x, const float* __restrict__ ln1g,
                            const float* __restrict__ ln1b,
                            unsigned short* __restrict__ owqkv, unsigned short* __restrict__ owo,
                            unsigned short* __restrict__ ow1, unsigned short* __restrict__ ow2,
                            float* __restrict__ obqkv, unsigned short* __restrict__ oh) {
    int bid = blockIdx.x;
    int t = threadIdx.y * 32 + threadIdx.x;
    if (bid >= 12300) {
        __shared__ float sh[8];
        int row = bid - 12300;
        size_t base = (size_t)row * DIM;
        float v0[4];
        float s = 0.f;
        #pragma unroll
        for (int u = 0; u < 4; u++) { v0[u] = x[base + t + u * 256]; s += v0[u]; }
        s = block_sum_256(s, sh, t);
        float mean = s * (1.0f / DIM);
        float vs = 0.f;
        #pragma unroll
        for (int u = 0; u < 4; u++) { float d = v0[u] - mean; vs += d * d; }
        vs = block_sum_256(vs, sh, t);
        float rstd = rsqrtf(vs * (1.0f / DIM) + 1e-5f);
        #pragma unroll
        for (int u = 0; u < 4; u++) {
            int c = t + u * 256;
            oh[base + c] = f2h((v0[u] - mean) * rstd * ln1g[c] + ln1b[c]);
        }
        return;
    }
    if (bid >= 12288) {
        int i = (bid - 12288) * 256 + t;
        if (i < DIM) obqkv[i] = bq[i];
        else if (i < 2 * DIM) obqkv[i] = bk[i - DIM];
        else obqkv[i] = bv[i - 2 * DIM];
        return;
    }
    const float* in;
    unsigned short* out;
    int R, C, l;
    if (bid < 4096) {
        l = bid & 1023;
        R = DIM; C = DIM;
        int m = bid >> 10;
        in  = (m == 0) ? wq : (m == 1) ? wk : (m == 2) ? wv : wo;
        out = (m == 3) ? owo : owqkv + (size_t)m * DIM * DIM;
    } else if (bid < 8192) {
        l = bid - 4096; R = DIM; C = MLPD; in = w1; out = ow1;
    } else {
        l = bid - 8192; R = MLPD; C = DIM; in = w2; out = ow2;
    }
    int nbx = C >> 5;
    int bx = l % nbx, by = l / nbx;
    __shared__ float tt[32][33];
    int c0 = bx * 32, r0 = by * 32;
    #pragma unroll
    for (int u = 0; u < 4; u++) {
        int r = r0 + threadIdx.y + u * 8;
        tt[threadIdx.y + u * 8][threadIdx.x] = in[(size_t)r * C + c0 + threadIdx.x];
    }
    __syncthreads();
    #pragma unroll
    for (int u = 0; u < 4; u++) {
        int c = c0 + threadIdx.y + u * 8;
        out[(size_t)c * R + r0 + threadIdx.x] = f2h(tt[threadIdx.x][threadIdx.y + u * 8]);
    }
}

// ---------------- fp16 GEMM 128x128 (double-barrier), optional split-K ----------------
#define TILEB 10240u
#define STAGES 4
#define GEMM_SMEM (STAGES * 2 * 10240)
#define QSCALE_F 0.1803368801111204f   // 0.125 * log2(e)

__global__ __launch_bounds__(256, 2)
void gemm_mma_kernel(const unsigned short* __restrict__ A, const unsigned short* __restrict__ B,
                     const float* __restrict__ bias, const float* __restrict__ res,
                     float* __restrict__ outF, unsigned short* __restrict__ outH,
                     float* __restrict__ outP,
                     int N, int K, int ld, int gelu, int qscale) {
    extern __shared__ char smem[];
    const uint32_t sb = smem_u32(smem);
    const int tid  = threadIdx.x;
    const int wid  = tid >> 5;
    const int lane = tid & 31;
    const int wm = wid >> 2;
    const int wn = wid & 3;
    const int bm = blockIdx.y * 128;
    const int bn = blockIdx.x * 128;
    const int g  = lane >> 2;
    const int t4 = lane & 3;

    const unsigned short* Az = A + (size_t)blockIdx.z * K;
    const unsigned short* Bz = B + (size_t)blockIdx.z * K;

    const uint32_t aOff = (uint32_t)((((lane >> 3) & 1) * 8 + (lane & 7)) * 80 + (lane >> 4) * 16);
    const uint32_t bOff = (uint32_t)(((lane >> 4) * 8 + (lane & 7)) * 80 + ((lane >> 3) & 1) * 16);

    float acc[4][4][4];
    #pragma unroll
    for (int i = 0; i < 4; i++)
        #pragma unroll
        for (int j = 0; j < 4; j++)
            #pragma unroll
            for (int q = 0; q < 4; q++) acc[i][j][q] = 0.f;

    const int NCH = K >> 5;
    const unsigned short* gsrc[2] = {Az, Bz};
    const int rbase[2] = {bm, bn};

    auto load_chunk = [&](int stage, int k0) {
        #pragma unroll
        for (int t = 0; t < 2; t++) {
            uint32_t dst = sb + (uint32_t)(stage * 2 + t) * TILEB;
            const unsigned short* gp = gsrc[t];
            #pragma unroll
            for (int u = 0; u < 2; u++) {
                int idx = tid + 256 * u;
                int r = idx >> 2;
                int cc = idx & 3;
                cp_async16(dst + (uint32_t)(r * 80 + cc * 16),
                           gp + (size_t)(rbase[t] + r) * ld + k0 + cc * 8);
            }
        }
        CP_COMMIT();
    };

    #pragma unroll
    for (int s = 0; s < STAGES; s++) load_chunk(s, s * 32);

    int st = 0;
    for (int i = 0; i < NCH; i++) {
        CP_WAIT(STAGES - 1);
        __syncthreads();

        const uint32_t aB = sb + (uint32_t)(st * 2) * TILEB;
        const uint32_t bB = aB + TILEB;

        #pragma unroll
        for (int ks = 0; ks < 2; ks++) {
            uint32_t bf[2][4];
            #pragma unroll
            for (int np = 0; np < 2; np++) {
                uint32_t o = (uint32_t)((wn * 32 + np * 16) * 80 + ks * 32) + bOff;
                LDSM4(bf[np], bB + o);
            }
            #pragma unroll
            for (int mt = 0; mt < 4; mt++) {
                uint32_t af[4];
                uint32_t o = (uint32_t)((wm * 64 + mt * 16) * 80 + ks * 32) + aOff;
                LDSM4(af, aB + o);
                #pragma unroll
                for (int nt = 0; nt < 4; nt++) {
                    int np = nt >> 1, sub = (nt & 1) * 2;
                    MMA_F16(acc[mt][nt], af, bf[np][sub], bf[np][sub + 1]);
                }
            }
        }
        __syncthreads();

        if (i + STAGES < NCH) load_chunk(st, (i + STAGES) * 32);
        else                  CP_COMMIT();
        st = (st + 1) & (STAGES - 1);
    }

    if (outP) {
        float* po = outP + (size_t)blockIdx.z * SQ * N;
        #pragma unroll
        for (int mt = 0; mt < 4; mt++) {
            int r0 = bm + wm * 64 + mt * 16 + g;
            #pragma unroll
            for (int nt = 0; nt < 4; nt++) {
                int c = bn + wn * 32 + nt * 8 + t4 * 2;
                *(float2*)(po + (size_t)r0 * N + c)       = make_float2(acc[mt][nt][0], acc[mt][nt][1]);
                *(float2*)(po + (size_t)(r0 + 8) * N + c) = make_float2(acc[mt][nt][2], acc[mt][nt][3]);
            }
        }
        return;
    }

    #pragma unroll
    for (int mt = 0; mt < 4; mt++) {
        int r0 = bm + wm * 64 + mt * 16 + g;
        #pragma unroll
        for (int nt = 0; nt < 4; nt++) {
            int c = bn + wn * 32 + nt * 8 + t4 * 2;
            float v[4];
            v[0] = acc[mt][nt][0] + bias[c];
            v[1] = acc[mt][nt][1] + bias[c + 1];
            v[2] = acc[mt][nt][2] + bias[c];
            v[3] = acc[mt][nt][3] + bias[c + 1];
            if (gelu) {
                #pragma unroll
                for (int q = 0; q < 4; q++)
                    v[q] = 0.5f * v[q] * (1.0f + erff(v[q] * 0.70710678118654752f));
            }
            if (qscale) {
                if (c < DIM)     { v[0] *= QSCALE_F; v[2] *= QSCALE_F; }
                if (c + 1 < DIM) { v[1] *= QSCALE_F; v[3] *= QSCALE_F; }
            }
            if (res) {
                v[0] += res[(size_t)r0 * N + c];
                v[1] += res[(size_t)r0 * N + c + 1];
                v[2] += res[(size_t)(r0 + 8) * N + c];
                v[3] += res[(size_t)(r0 + 8) * N + c + 1];
            }
            if (outF) {
                *(float2*)(outF + (size_t)r0 * N + c)       = make_float2(v[0], v[1]);
                *(float2*)(outF + (size_t)(r0 + 8) * N + c) = make_float2(v[2], v[3]);
            } else {
                *(uint32_t*)(outH + (size_t)r0 * N + c)       = pack2_h(v[0], v[1]);
                *(uint32_t*)(outH + (size_t)(r0 + 8) * N + c) = pack2_h(v[2], v[3]);
            }
        }
    }
}

// ---------------- split-K reduce (FFN2): out = p0 + p1 + bias + res ----------------
__global__ void reduce2_kernel(const float* __restrict__ p0, const float* __restrict__ p1,
                               const float* __restrict__ bias, const float* __restrict__ res,
                               float* __restrict__ out) {
    size_t i = ((size_t)blockIdx.x * 256 + threadIdx.x) * 4;
    int c = (int)(i & (DIM - 1));
    float4 a = *(const float4*)(p0 + i);
    float4 b = *(const float4*)(p1 + i);
    float4 r = *(const float4*)(res + i);
    float4 o;
    o.x = a.x + b.x + bias[c]     + r.x;
    o.y = a.y + b.y + bias[c + 1] + r.y;
    o.z = a.z + b.z + bias[c + 2] + r.z;
    o.w = a.w + b.w + bias[c + 3] + r.w;
    *(float4*)(out + i) = o;
}

// ---------------- flash attention, split-KV (z=2), exp2 domain ----------------
#define ATILE 9216u
#define ATT_SMEM (2 * 2 * 9216)

__global__ __launch_bounds__(128)
void attn_mma_kernel(const unsigned short* __restrict__ qkv,
                     float* __restrict__ partO, float* __restrict__ ml) {
    extern __shared__ char smem[];
    const uint32_t sb = smem_u32(smem);
    const int h  = blockIdx.y;
    const int q0 = blockIdx.x * 64;
    const int z  = blockIdx.z;
    const int kbase = z * (SQ / 2);
    const int tid = threadIdx.x;
    const int w = tid >> 5, lane = tid & 31;
    const int g = lane >> 2, t4 = lane & 3;
    const int qcol = h * HDK, kcol = DIM + h * HDK, vcol = 2 * DIM + h * HDK;

    const uint32_t aOff = (uint32_t)((((lane >> 3) & 1) * 8 + (lane & 7)) * 144 + (lane >> 4) * 16);
    const uint32_t bOff = (uint32_t)(((lane >> 4) * 8 + (lane & 7)) * 144 + ((lane >> 3) & 1) * 16);
    const uint32_t vOff = (uint32_t)((lane & 15) * 144 + (lane >> 4) * 16);

    #define AK(s) (sb + (uint32_t)(s) * 2u * ATILE)
    #define AV(s) (AK(s) + ATILE)

    #pragma unroll
    for (int u = 0; u < 4; u++) {
        int idx = tid + u * 128;
        int row = idx >> 3, c16 = idx & 7;
        cp_async16(AK(0) + (uint32_t)(row * 144 + c16 * 16),
                   qkv + (size_t)(q0 + row) * QKVN + qcol + c16 * 8);
    }
    CP_COMMIT(); CP_WAIT(0); __syncthreads();

    uint32_t qh[4][4];
    #pragma unroll
    for (int ks = 0; ks < 4; ks++) {
        uint32_t o = (uint32_t)(w * 16 * 144 + ks * 32);
        LDSM4(qh[ks], AK(0) + o + aOff);
    }
    __syncthreads();

    auto load_kv = [&](int st, int kt) {
        #pragma unroll
        for (int u = 0; u < 4; u++) {
            int idx = tid + u * 128;
            int row = idx >> 3, c16 = idx & 7;
            uint32_t off = (uint32_t)(row * 144 + c16 * 16);
            cp_async16(AK(st) + off, qkv + (size_t)(kt + row) * QKVN + kcol + c16 * 8);
            cp_async16(AV(st) + off, qkv + (size_t)(kt + row) * QKVN + vcol + c16 * 8);
        }
        CP_COMMIT();
    };
    load_kv(0, kbase);
    load_kv(1, kbase + 64);

    float of[8][4];
    #pragma unroll
    for (int j = 0; j < 8; j++)
        #pragma unroll
        for (int q = 0; q < 4; q++) of[j][q] = 0.f;
    float m0 = -1e30f, m1 = -1e30f, l0 = 0.f, l1 = 0.f;

    const int NIT = SQ / 128;
    for (int it = 0; it < NIT; it++) {
        CP_WAIT(1);
        __syncthreads();
        const int st = it & 1;

        float sf[8][4];
        #pragma unroll
        for (int j = 0; j < 8; j++)
            #pragma unroll
            for (int q = 0; q < 4; q++) sf[j][q] = 0.f;

        #pragma unroll
        for (int ks = 0; ks < 4; ks++) {
            #pragma unroll
            for (int nb = 0; nb < 4; nb++) {
                uint32_t kf[4];
                LDSM4(kf, AK(st) + (uint32_t)(nb * 16 * 144 + ks * 32) + bOff);
                MMA_F16(sf[2*nb],   qh[ks], kf[0], kf[1]);
                MMA_F16(sf[2*nb+1], qh[ks], kf[2], kf[3]);
            }
        }

        float mx0 = -1e30f, mx1 = -1e30f;
        #pragma unroll
        for (int j = 0; j < 8; j++) {
            mx0 = fmaxf(mx0, fmaxf(sf[j][0], sf[j][1]));
            mx1 = fmaxf(mx1, fmaxf(sf[j][2], sf[j][3]));
        }
        mx0 = fmaxf(mx0, __shfl_xor_sync(0xffffffffu, mx0, 1));
        mx0 = fmaxf(mx0, __shfl_xor_sync(0xffffffffu, mx0, 2));
        mx1 = fmaxf(mx1, __shfl_xor_sync(0xffffffffu, mx1, 1));
        mx1 = fmaxf(mx1, __shfl_xor_sync(0xffffffffu, mx1, 2));
        float mn0 = fmaxf(m0, mx0), mn1 = fmaxf(m1, mx1);
        float sc0 = exp2f(m0 - mn0), sc1 = exp2f(m1 - mn1);
        m0 = mn0; m1 = mn1;
        float s0 = 0.f, s1 = 0.f;
        #pragma unroll
        for (int j = 0; j < 8; j++) {
            sf[j][0] = exp2f(sf[j][0] - mn0); s0 += sf[j][0];
            sf[j][1] = exp2f(sf[j][1] - mn0); s0 += sf[j][1];
            sf[j][2] = exp2f(sf[j][2] - mn1); s1 += sf[j][2];
            sf[j][3] = exp2f(sf[j][3] - mn1); s1 += sf[j][3];
        }
        s0 += __shfl_xor_sync(0xffffffffu, s0, 1);
        s0 += __shfl_xor_sync(0xffffffffu, s0, 2);
        s1 += __shfl_xor_sync(0xffffffffu, s1, 1);
        s1 += __shfl_xor_sync(0xffffffffu, s1, 2);
        l0 = l0 * sc0 + s0;
        l1 = l1 * sc1 + s1;
        #pragma unroll
        for (int j = 0; j < 8; j++) {
            of[j][0] *= sc0; of[j][1] *= sc0;
            of[j][2] *= sc1; of[j][3] *= sc1;
        }

        #pragma unroll
        for (int jp = 0; jp < 4; jp++) {
            uint32_t p0 = pack2_h(sf[2*jp][0],   sf[2*jp][1]);
            uint32_t p1 = pack2_h(sf[2*jp][2],   sf[2*jp][3]);
            uint32_t p2 = pack2_h(sf[2*jp+1][0], sf[2*jp+1][1]);
            uint32_t p3 = pack2_h(sf[2*jp+1][2], sf[2*jp+1][3]);
            #pragma unroll
            for (int nb = 0; nb < 4; nb++) {
                uint32_t vf[4];
                LDSM4T(vf, AV(st) + (uint32_t)(jp * 16 * 144 + nb * 16 * 2) + vOff);
                MMA_F16R(of[2*nb],   p0, p1, p2, p3, vf[0], vf[1]);
                MMA_F16R(of[2*nb+1], p0, p1, p2, p3, vf[2], vf[3]);
            }
        }

        __syncthreads();
        if (it + 2 < NIT) load_kv(st, kbase + (it + 2) * 64);
        else              CP_COMMIT();
    }

    float* po = partO + (size_t)z * SQ * DIM;
    float* mlz = ml + (size_t)z * 2 * NHSQ;
    int rg0 = h * SQ + q0 + w * 16 + g;
    if (t4 == 0) {
        mlz[rg0]            = m0;
        mlz[NHSQ + rg0]     = l0;
        mlz[rg0 + 8]        = m1;
        mlz[NHSQ + rg0 + 8] = l1;
    }
    #pragma unroll
    for (int j = 0; j < 8; j++) {
        int d = 8 * j + 2 * t4;
        *(float2*)(po + (size_t)rg0 * HDK + d)       = make_float2(of[j][0], of[j][1]);
        *(float2*)(po + (size_t)(rg0 + 8) * HDK + d) = make_float2(of[j][2], of[j][3]);
    }
}

// ---------------- split-KV merge -> ao fp16 (vectorized: 4 elems/thread) ----------------
__global__ void attn_merge_kernel(const float* __restrict__ p0, const float* __restrict__ p1,
                                  const float* __restrict__ ml, unsigned short* __restrict__ O) {
    int idx4 = blockIdx.x * 256 + threadIdx.x;   // over NHSQ*HDK/4 float4 groups
    int r = idx4 >> 4;                           // 16 float4 per 64-elem row
    float m0 = ml[r],            l0 = ml[NHSQ + r];
    float m1 = ml[2 * NHSQ + r], l1 = ml[3 * NHSQ + r];
    float m = fmaxf(m0, m1);
    float w0 = exp2f(m0 - m), w1 = exp2f(m1 - m);
    float inv = 1.0f / (l0 * w0 + l1 * w1);
    w0 *= inv; w1 *= inv;
    float4 a = *(const float4*)(p0 + (size_t)idx4 * 4);
    float4 b = *(const float4*)(p1 + (size_t)idx4 * 4);
    uint2 o;
    o.x = pack2_h(a.x * w0 + b.x * w1, a.y * w0 + b.y * w1);
    o.y = pack2_h(a.z * w0 + b.z * w1, a.w * w0 + b.w * w1);
    *(uint2*)(O + (size_t)idx4 * 4) = o;
}

// ---------------- launch ----------------
extern "C" void kernel_launch(void* const* d_in, const int* in_sizes, int n_in,
                              void* d_out, int out_size) {
    const float* x     = (const float*)d_in[0];
    const float* wq    = (const float*)d_in[1];
    const float* bq    = (const float*)d_in[2];
    const float* wk    = (const float*)d_in[3];
    const float* bk    = (const float*)d_in[4];
    const float* wv    = (const float*)d_in[5];
    const float* bv    = (const float*)d_in[6];
    const float* wo    = (const float*)d_in[7];
    const float* bo    = (const float*)d_in[8];
    const float* w1    = (const float*)d_in[9];
    const float* b1    = (const float*)d_in[10];
    const float* w2    = (const float*)d_in[11];
    const float* b2    = (const float*)d_in[12];
    const float* ln1_g = (const float*)d_in[13];
    const float* ln1_b = (const float*)d_in[14];
    const float* ln2_g = (const float*)d_in[15];
    const float* ln2_b = (const float*)d_in[16];
    float* out = (float*)d_out;

    unsigned short *hh, *qkv, *ao, *f, *wqkvh, *woh, *w1h, *w2h;
    float *x1, *bqkv, *part, *ml;
    cudaGetSymbolAddress((void**)&hh,   g_h);
    cudaGetSymbolAddress((void**)&qkv,  g_qkv);
    cudaGetSymbolAddress((void**)&ao,   g_ao);
    cudaGetSymbolAddress((void**)&x1,   g_x1);
    cudaGetSymbolAddress((void**)&f,    g_f);
    cudaGetSymbolAddress((void**)&wqkvh, g_wqkv);
    cudaGetSymbolAddress((void**)&woh,  g_wo);
    cudaGetSymbolAddress((void**)&w1h,  g_w1);
    cudaGetSymbolAddress((void**)&w2h,  g_w2);
    cudaGetSymbolAddress((void**)&bqkv, g_bqkv);
    cudaGetSymbolAddress((void**)&part, g_part);
    cudaGetSymbolAddress((void**)&ml,   g_ml);

    cudaFuncSetAttribute(gemm_mma_kernel,
                         cudaFuncAttributeMaxDynamicSharedMemorySize, GEMM_SMEM);
    cudaFuncSetAttribute(attn_mma_kernel,
                         cudaFuncAttributeMaxDynamicSharedMemorySize, ATT_SMEM);

    // prep: weights + bias + LN1 in one launch
    prep_kernel<<<14348, dim3(32, 8)>>>(wq, wk, wv, wo, w1, w2, bq, bk, bv,
                                        x, ln1_g, ln1_b,
                                        wqkvh, woh, w1h, w2h, bqkv, hh);
    // QKV fused GEMM -> fp16 (q pre-scaled by 0.125*log2e)
    gemm_mma_kernel<<<dim3(QKVN/128, SQ/128), 256, GEMM_SMEM>>>(
        hh, wqkvh, bqkv, nullptr, nullptr, qkv, nullptr, QKVN, DIM, DIM, 0, 1);
    // attention split-KV (z=2) -> partials, then merge -> ao fp16
    attn_mma_kernel<<<dim3(SQ/64, NH, 2), 128, ATT_SMEM>>>(qkv, part, ml);
    attn_merge_kernel<<<NHSQ * HDK / 1024, 256>>>(part, part + (size_t)SQ * DIM, ml, ao);
    // O-proj split-K=2 -> partials
    gemm_mma_kernel<<<dim3(DIM/128, SQ/128, 2), 256, GEMM_SMEM>>>(
        ao, woh, nullptr, nullptr, nullptr, nullptr, part, DIM, DIM/2, DIM, 0, 0);
    // fused reduce + bias + residual(x) + LN2 -> x1, hh
    reduce_ln_kernel<<<SQ, 256>>>(part, part + (size_t)SQ * DIM, bo, x,
                                  ln2_g, ln2_b, x1, hh);
    // FFN1 + GELU -> f fp16
    gemm_mma_kernel<<<dim3(MLPD/128, SQ/128), 256, GEMM_SMEM>>>(
        hh, w1h, b1, nullptr, nullptr, f, nullptr, MLPD, DIM, DIM, 1, 0);
    // FFN2 split-K=2 -> partials, then reduce -> out
    gemm_mma_kernel<<<dim3(DIM/128, SQ/128, 2), 256, GEMM_SMEM>>>(
        f, w2h, nullptr, nullptr, nullptr, nullptr, part, DIM, MLPD/2, MLPD, 0, 0);
    reduce2_kernel<<<SQ * DIM / 1024, 256>>>(part, part + (size_t)SQ * DIM, b2, x1, out);
}